// round 11
// baseline (speedup 1.0000x reference)
#include <cuda_runtime.h>
#include <cstdint>
#include <math.h>

// Problem dims (fixed)
#define B_      2
#define L_      2048
#define D_      2048
#define M_      4096          // B*L
#define H_      16
#define DK      64
#define DV      128
#define NQK     1024          // H*DK
#define CHUNK   64
#define NCHUNK  32            // L / CHUNK
#define SCALE_QK 0.08838834764831845f   // 128^-0.5
#define INV_NORM 0.0625f                 // 1/16
#define LN_EPS   1e-5f

// ---------------- scratch (static device globals; no allocation) -------------
__device__ float g_q   [(size_t)M_ * NQK];   // after prep: q * e^G
__device__ float g_k   [(size_t)M_ * NQK];   // after prep: k * e^-G (pre-scaled)
__device__ float g_gate[(size_t)M_ * NQK];
__device__ float g_kg1 [(size_t)M_ * 16];
__device__ float g_v   [(size_t)M_ * D_];
__device__ float g_gp  [(size_t)M_ * D_];
__device__ float g_y   [(size_t)M_ * D_];    // written tf32-rounded
__device__ float g_S   [(size_t)B_ * H_ * NCHUNK * DK * DV];
__device__ float g_E   [(size_t)B_ * H_ * NCHUNK * DK];      // per-chunk decay
__device__ float g_x   [(size_t)M_ * D_];    // tf32-rounded x
__device__ float g_w   [(size_t)8192 * D_];  // tf32-rounded Wq|Wk|Wv|Wg|Wo

#define WOFF_Q  0
#define WOFF_K  ((size_t)1024 * D_)
#define WOFF_V  ((size_t)2048 * D_)
#define WOFF_G  ((size_t)4096 * D_)
#define WOFF_O  ((size_t)6144 * D_)

// ======================= PTX helpers (non-'a' features only) ==================
__device__ __forceinline__ uint32_t smem_u32(const void* p) {
    uint32_t a;
    asm("{ .reg .u64 t; cvta.to.shared.u64 t, %1; cvt.u32.u64 %0, t; }" : "=r"(a) : "l"(p));
    return a;
}
__device__ __forceinline__ void cp_async16(uint32_t dst, const void* src) {
    asm volatile("cp.async.cg.shared.global [%0], [%1], 16;" :: "r"(dst), "l"(src) : "memory");
}
#define CP_COMMIT() asm volatile("cp.async.commit_group;" ::: "memory")
#define CP_WAIT(N)  asm volatile("cp.async.wait_group %0;" :: "n"(N) : "memory")

__device__ __forceinline__ uint32_t f2tf(float f) {
    uint32_t u;
    asm("cvt.rna.tf32.f32 %0, %1;" : "=r"(u) : "f"(f));
    return u;
}
__device__ __forceinline__ void mma_tf32(float c[4], const uint32_t a[4], const uint32_t b[2]) {
    asm volatile(
        "mma.sync.aligned.m16n8k8.row.col.f32.tf32.tf32.f32 "
        "{%0,%1,%2,%3}, {%4,%5,%6,%7}, {%8,%9}, {%0,%1,%2,%3};"
        : "+f"(c[0]), "+f"(c[1]), "+f"(c[2]), "+f"(c[3])
        : "r"(a[0]), "r"(a[1]), "r"(a[2]), "r"(a[3]), "r"(b[0]), "r"(b[1]));
}

// ---------------- fused tf32 rounding pass (segmented) ------------------------
__global__ __launch_bounds__(256) void rnd_all_kernel(
    const float4* __restrict__ x,
    const float4* __restrict__ Wq, const float4* __restrict__ Wk,
    const float4* __restrict__ Wv, const float4* __restrict__ Wg,
    const float4* __restrict__ Wo,
    float4* __restrict__ dx, float4* __restrict__ dw)
{
    const int seg = blockIdx.y;
    const float4* src;
    float4* dst;
    int n4;
    switch (seg) {
        case 0: src = x;  dst = dx;            n4 = M_*D_/4;   break;
        case 1: src = Wq; dst = dw + WOFF_Q/4; n4 = 1024*D_/4; break;
        case 2: src = Wk; dst = dw + WOFF_K/4; n4 = 1024*D_/4; break;
        case 3: src = Wv; dst = dw + WOFF_V/4; n4 = 2048*D_/4; break;
        case 4: src = Wg; dst = dw + WOFF_G/4; n4 = 2048*D_/4; break;
        default:src = Wo; dst = dw + WOFF_O/4; n4 = 2048*D_/4; break;
    }
    int i = blockIdx.x * blockDim.x + threadIdx.x;
    if (i < n4) {
        float4 v = src[i];
        float4 o;
        o.x = __uint_as_float(f2tf(v.x));
        o.y = __uint_as_float(f2tf(v.y));
        o.z = __uint_as_float(f2tf(v.z));
        o.w = __uint_as_float(f2tf(v.w));
        dst[i] = o;
    }
}

// ======================= tf32 GEMM (mma.sync), multi-target ===================
// 512 threads, 16 warps (4x4), warp tile 32x32 (2x4 m16n8 tiles).
// Tile 128x128x32, cp.async double-buffered. ~80 regs/thread -> no spills,
// 16 warps/SM for latency hiding.
#define BM 128
#define BN 128
#define BK 32
#define GTHR 512
#define PITCH 36
#define TSTRIDE (128*PITCH)
#define GEMM_SMEM_BYTES (4*TSTRIDE*4)

__global__ __launch_bounds__(GTHR, 1)
void tf32_gemm_multi(
    const float* __restrict__ A,
    const float* __restrict__ W0, const float* __restrict__ W1,
    const float* __restrict__ W2, const float* __restrict__ W3,
    const float* __restrict__ bias3,
    float* __restrict__ C0, float* __restrict__ C1,
    float* __restrict__ C2, float* __restrict__ C3,
    int K,
    int s1, int s2, int s3,
    int cb1, int cb2, int cb3,
    int N0, int N1, int N2, int N3,
    float a0, float a1, float a2, float a3)
{
    extern __shared__ float smf[];
    float* Asm = smf;
    float* Bsm = smf + 2*TSTRIDE;
    const uint32_t Abase_s = smem_u32(Asm);
    const uint32_t Bbase_s = smem_u32(Bsm);

    const int c = blockIdx.x;
    const int sel = (c >= s3) ? 3 : (c >= s2) ? 2 : (c >= s1) ? 1 : 0;
    const float* W = (sel == 0) ? W0 : (sel == 1) ? W1 : (sel == 2) ? W2 : W3;
    float*       C = (sel == 0) ? C0 : (sel == 1) ? C1 : (sel == 2) ? C2 : C3;
    const int start   = (sel == 0) ? 0 : (sel == 1) ? s1 : (sel == 2) ? s2 : s3;
    const int colbase = (sel == 0) ? 0 : (sel == 1) ? cb1 : (sel == 2) ? cb2 : cb3;
    const int N       = (sel == 0) ? N0 : (sel == 1) ? N1 : (sel == 2) ? N2 : N3;
    const float alpha = (sel == 0) ? a0 : (sel == 1) ? a1 : (sel == 2) ? a2 : a3;
    const float* bias = (sel == 3) ? bias3 : nullptr;

    const int tid = threadIdx.x;
    const int wid = tid >> 5;
    const int lane = tid & 31;
    const int g  = lane >> 2;        // 0..7
    const int t4 = lane & 3;         // 0..3
    const int wm = wid >> 2;         // 0..3 -> 32-row block
    const int wn = wid & 3;          // 0..3 -> 32-col block
    const int m0 = blockIdx.y * BM;
    const int wrow = (c - start) * BN;   // tile-local row offset inside W
    const int n0g = wrow + colbase;      // global output column base

    const float* Ag = A + (size_t)m0   * K;
    const float* Bg = W + (size_t)wrow * K;

    float cacc[2][4][4];
#pragma unroll
    for (int i = 0; i < 2; ++i)
#pragma unroll
        for (int j = 0; j < 4; ++j)
#pragma unroll
            for (int e = 0; e < 4; ++e) cacc[i][j][e] = 0.f;

    const int niter = K / BK;

    auto load_tile = [&](int kt, int s) {
        const int k0 = kt * BK;
        const uint32_t sa = Abase_s + (uint32_t)s * TSTRIDE * 4;
        const uint32_t sb = Bbase_s + (uint32_t)s * TSTRIDE * 4;
#pragma unroll
        for (int i = 0; i < 2; ++i) {
            int idx = tid + GTHR*i;          // 0..1023
            int r = idx >> 3, sg = idx & 7;
            cp_async16(sa + (uint32_t)(r*PITCH + sg*4)*4, Ag + (size_t)r*K + k0 + sg*4);
        }
#pragma unroll
        for (int i = 0; i < 2; ++i) {
            int idx = tid + GTHR*i;
            int r = idx >> 3, sg = idx & 7;
            cp_async16(sb + (uint32_t)(r*PITCH + sg*4)*4, Bg + (size_t)r*K + k0 + sg*4);
        }
    };

    load_tile(0, 0);
    CP_COMMIT();

    for (int kt = 0; kt < niter; ++kt) {
        const int s = kt & 1;
        if (kt + 1 < niter) {
            load_tile(kt + 1, s ^ 1);
            CP_COMMIT();
            CP_WAIT(1);
        } else {
            CP_WAIT(0);
        }
        __syncthreads();

        const uint32_t* As = (const uint32_t*)(Asm + s * TSTRIDE);
        const uint32_t* Bs = (const uint32_t*)(Bsm + s * TSTRIDE);
#pragma unroll
        for (int kk = 0; kk < 4; ++kk) {
            uint32_t af[2][4];
#pragma unroll
            for (int mt = 0; mt < 2; ++mt) {
                const int r0 = wm*32 + mt*16 + g;
                const uint32_t* pa = As + kk*8 + t4;
                af[mt][0] = pa[(r0    )*PITCH    ];
                af[mt][1] = pa[(r0 + 8)*PITCH    ];
                af[mt][2] = pa[(r0    )*PITCH + 4];
                af[mt][3] = pa[(r0 + 8)*PITCH + 4];
            }
            uint32_t bf[4][2];
#pragma unroll
            for (int nt = 0; nt < 4; ++nt) {
                const int nr = wn*32 + nt*8 + g;
                const uint32_t* pb = Bs + (size_t)nr*PITCH + kk*8 + t4;
                bf[nt][0] = pb[0];
                bf[nt][1] = pb[4];
            }
#pragma unroll
            for (int mt = 0; mt < 2; ++mt)
#pragma unroll
                for (int nt = 0; nt < 4; ++nt)
                    mma_tf32(cacc[mt][nt], af[mt], bf[nt]);
        }
        __syncthreads();
    }

#pragma unroll
    for (int mt = 0; mt < 2; ++mt) {
#pragma unroll
        for (int nt = 0; nt < 4; ++nt) {
            const int col = n0g + wn*32 + nt*8 + 2*t4;
            float b0 = bias ? __ldg(bias + col)     : 0.f;
            float b1 = bias ? __ldg(bias + col + 1) : 0.f;
            const int r0 = m0 + wm*32 + mt*16 + g;
            float2 v0 = make_float2(cacc[mt][nt][0]*alpha + b0, cacc[mt][nt][1]*alpha + b1);
            float2 v1 = make_float2(cacc[mt][nt][2]*alpha + b0, cacc[mt][nt][3]*alpha + b1);
            *(float2*)(C + (size_t)r0      * N + col) = v0;
            *(float2*)(C + (size_t)(r0+8)  * N + col) = v1;
        }
    }
}

// ---------------- kg1 = x @ Wkg1^T  ------------------------------------------
__global__ __launch_bounds__(256) void kg1_kernel(
    const float* __restrict__ x, const float* __restrict__ Wkg1,
    float* __restrict__ out)
{
    __shared__ float xs[16][68];
    __shared__ float ws[16][68];
    const int tid = threadIdx.x;
    const int tx = tid & 15;
    const int ty = tid >> 4;
    const int m0 = blockIdx.x * 16;
    const int lrow = tid >> 4;
    const int lcol = (tid & 15) * 4;
    float acc = 0.f;
    for (int kt = 0; kt < D_; kt += 64) {
        float4 xv = *(const float4*)(x    + (size_t)(m0 + lrow)*D_ + kt + lcol);
        float4 wv = *(const float4*)(Wkg1 + (size_t)lrow*D_        + kt + lcol);
        *(float4*)&xs[lrow][lcol] = xv;
        *(float4*)&ws[lrow][lcol] = wv;
        __syncthreads();
#pragma unroll
        for (int kk = 0; kk < 64; ++kk)
            acc = fmaf(xs[ty][kk], ws[tx][kk], acc);
        __syncthreads();
    }
    out[(size_t)(m0 + ty)*16 + tx] = acc;
}

// ---------------- gate = log_sigmoid(kg1 @ Wkg2^T + bkg2) / 16 ---------------
__global__ __launch_bounds__(256) void gate_kernel(
    const float* __restrict__ Wkg2, const float* __restrict__ bkg2)
{
    __shared__ float row[16];
    const int tid = threadIdx.x;
    const int m = blockIdx.x;
    if (tid < 16) row[tid] = g_kg1[(size_t)m*16 + tid];
    __syncthreads();
#pragma unroll
    for (int i = 0; i < 4; ++i) {
        int n = i*256 + tid;
        const float4* wp = (const float4*)(Wkg2 + (size_t)n*16);
        float4 w0 = wp[0], w1 = wp[1], w2 = wp[2], w3 = wp[3];
        float acc = bkg2[n];
        acc += row[0]*w0.x + row[1]*w0.y + row[2]*w0.z + row[3]*w0.w;
        acc += row[4]*w1.x + row[5]*w1.y + row[6]*w1.z + row[7]*w1.w;
        acc += row[8]*w2.x + row[9]*w2.y + row[10]*w2.z + row[11]*w2.w;
        acc += row[12]*w3.x + row[13]*w3.y + row[14]*w3.z + row[15]*w3.w;
        float z = acc;
        float e  = __expf(-fabsf(z));
        float ls = fminf(z, 0.f) - __logf(1.f + e);
        g_gate[(size_t)m*NQK + n] = ls * INV_NORM;
    }
}

// ---------------- prep: cumsum gates, transform q/k in place, store E --------
__global__ __launch_bounds__(64) void prep_kernel()
{
    const int c  = blockIdx.x;
    const int bh = blockIdx.y;
    const int b = bh >> 4, h = bh & 15;
    const int d = threadIdx.x;
    const int m0 = b * L_ + c * CHUNK;
    size_t gi = (size_t)m0 * NQK + h * DK + d;
    float run = 0.f;
    for (int t = 0; t < CHUNK; ++t) {
        run += g_gate[gi];
        float eg = __expf(run);
        float en = __expf(-run);
        g_q[gi] *= eg;
        g_k[gi] *= en;
        gi += NQK;
    }
    g_E[(size_t)(bh * NCHUNK + c) * DK + d] = __expf(run);
}

// ---------------- pass 1: chunk states, cp.async pipelined -------------------
#define SKP_K 68
#define SKP_V 36
#define STATE_SMEM ((2*64*SKP_K + 2*64*SKP_V)*4)

__global__ __launch_bounds__(128) void state_kernel()
{
    extern __shared__ float sms[];
    float* khs = sms;                    // [2][64][SKP_K]
    float* vvs = sms + 2*64*SKP_K;       // [2][64][SKP_V]
    const uint32_t kh_s = smem_u32(khs);
    const uint32_t vv_s = smem_u32(vvs);

    const int bq = blockIdx.x;
    const int bh = blockIdx.y;
    const int b = bh >> 4, h = bh & 15;
    const int tid = threadIdx.x;
    const int ty = tid >> 3;
    const int tx = tid & 7;
    const int mb = b * L_;

    auto prefetch = [&](int c, int s) {
        const int m0 = mb + c * CHUNK;
        const uint32_t ka = kh_s + (uint32_t)s * 64*SKP_K*4;
        const uint32_t va = vv_s + (uint32_t)s * 64*SKP_V*4;
#pragma unroll
        for (int i = 0; i < 8; ++i) {
            int e = tid + 128*i;
            int t = e >> 4, q4 = (e & 15) * 4;
            cp_async16(ka + (uint32_t)(t*SKP_K + q4)*4,
                       g_k + (size_t)(m0 + t)*NQK + h*DK + q4);
        }
#pragma unroll
        for (int i = 0; i < 4; ++i) {
            int e = tid + 128*i;
            int t = e >> 3, q4 = (e & 7) * 4;
            cp_async16(va + (uint32_t)(t*SKP_V + q4)*4,
                       g_v + (size_t)(m0 + t)*D_ + h*DV + bq*32 + q4);
        }
    };

    float S[4][4];
#pragma unroll
    for (int dd = 0; dd < 4; ++dd)
#pragma unroll
        for (int jj = 0; jj < 4; ++jj) S[dd][jj] = 0.f;

    prefetch(0, 0);
    CP_COMMIT();

    for (int c = 0; c < NCHUNK; ++c) {
        const int s = c & 1;
        CP_WAIT(0);
        __syncthreads();
        if (c + 1 < NCHUNK) {
            prefetch(c + 1, s ^ 1);
            CP_COMMIT();
        }

        float* sp = g_S + (size_t)(bh * NCHUNK + c) * (DK * DV) + (size_t)bq * 32;
#pragma unroll
        for (int dd = 0; dd < 4; ++dd)
            *(float4*)(sp + (size_t)(ty*4 + dd)*DV + tx*4) =
                make_float4(S[dd][0], S[dd][1], S[dd][2], S[dd][3]);

        float acc[4][4];
#pragma unroll
        for (int dd = 0; dd < 4; ++dd)
#pragma unroll
            for (int jj = 0; jj < 4; ++jj) acc[dd][jj] = 0.f;

        const float* kb = khs + s * 64*SKP_K;
        const float* vb = vvs + s * 64*SKP_V;
        for (int t = 0; t < CHUNK; ++t) {
            float4 kv = *(const float4*)(kb + t*SKP_K + ty*4);
            float4 vv4 = *(const float4*)(vb + t*SKP_V + tx*4);
            float ka[4] = {kv.x, kv.y, kv.z, kv.w};
            float va[4] = {vv4.x, vv4.y, vv4.z, vv4.w};
#pragma unroll
            for (int dd = 0; dd < 4; ++dd)
#pragma unroll
                for (int jj = 0; jj < 4; ++jj)
                    acc[dd][jj] = fmaf(ka[dd], va[jj], acc[dd][jj]);
        }

        const float* ep = g_E + (size_t)(bh * NCHUNK + c) * DK + ty*4;
        float E[4] = {ep[0], ep[1], ep[2], ep[3]};
#pragma unroll
        for (int dd = 0; dd < 4; ++dd)
#pragma unroll
            for (int jj = 0; jj < 4; ++jj)
                S[dd][jj] = E[dd] * (S[dd][jj] + acc[dd][jj]);
    }
}

// ---------------- pass 2: chunk outputs + LN + SiLU gating --------------------
#define OUT_SMEM ((2*64*68 + 64*65 + 64*132)*4)

__global__ __launch_bounds__(256) void output_kernel()
{
    extern __shared__ float sm[];
    float (*qs)[68]  = (float(*)[68]) sm;
    float (*ks)[68]  = (float(*)[68])(sm + 64*68);
    float (*GA)[65]  = (float(*)[65])(sm + 2*64*68);
    float (*buf)[132]= (float(*)[132])(sm + 2*64*68 + 64*65);   // Sp, then V

    const int c  = blockIdx.x;
    const int bh = blockIdx.y;
    const int b = bh >> 4, h = bh & 15;
    const int tid = threadIdx.x;
    const int m0 = b * L_ + c * CHUNK;
    const size_t sbase = (size_t)(bh * NCHUNK + c) * (DK * DV);

    for (int e = tid; e < CHUNK*DK; e += 256) {
        int t = e >> 6, d = e & 63;
        size_t gi = (size_t)(m0 + t)*NQK + h*DK + d;
        qs[t][d] = g_q[gi];
        ks[t][d] = g_k[gi];
    }
    for (int e = tid; e < DK*DV; e += 256) {
        int t = e >> 7, j = e & 127;
        buf[t][j] = g_S[sbase + e];
    }
    __syncthreads();

    for (int e = tid; e < CHUNK*CHUNK; e += 256) {
        int t = e >> 6, s = e & 63;
        float acc = 0.f;
        if (s <= t) {
            const float4* qp = (const float4*)&qs[t][0];
            const float4* kp = (const float4*)&ks[s][0];
#pragma unroll
            for (int d4 = 0; d4 < 16; ++d4) {
                float4 qa = qp[d4], kk4 = kp[d4];
                acc = fmaf(qa.x, kk4.x, acc);
                acc = fmaf(qa.y, kk4.y, acc);
                acc = fmaf(qa.z, kk4.z, acc);
                acc = fmaf(qa.w, kk4.w, acc);
            }
        }
        GA[t][s] = acc;
    }

    const int t  = tid >> 2;
    const int qq = tid & 3;
    float o[32];
#pragma unroll
    for (int jj = 0; jj < 32; ++jj) o[jj] = 0.f;

    for (int d = 0; d < DK; ++d) {
        float qv = qs[t][d];
        const float4* sp4 = (const float4*)&buf[d][qq*32];
#pragma unroll
        for (int j4 = 0; j4 < 8; ++j4) {
            float4 vv = sp4[j4];
            o[j4*4+0] = fmaf(qv, vv.x, o[j4*4+0]);
            o[j4*4+1] = fmaf(qv, vv.y, o[j4*4+1]);
            o[j4*4+2] = fmaf(qv, vv.z, o[j4*4+2]);
            o[j4*4+3] = fmaf(qv, vv.w, o[j4*4+3]);
        }
    }
    __syncthreads();
    for (int e = tid; e < CHUNK*DV; e += 256) {
        int s = e >> 7, j = e & 127;
        buf[s][j] = g_v[(size_t)(m0 + s)*D_ + h*DV + j];
    }
    __syncthreads();
    for (int s = 0; s <= t; ++s) {
        float av = GA[t][s];
        const float4* vp4 = (const float4*)&buf[s][qq*32];
#pragma unroll
        for (int j4 = 0; j4 < 8; ++j4) {
            float4 vv = vp4[j4];
            o[j4*4+0] = fmaf(av, vv.x, o[j4*4+0]);
            o[j4*4+1] = fmaf(av, vv.y, o[j4*4+1]);
            o[j4*4+2] = fmaf(av, vv.z, o[j4*4+2]);
            o[j4*4+3] = fmaf(av, vv.w, o[j4*4+3]);
        }
    }

    float s1 = 0.f;
#pragma unroll
    for (int jj = 0; jj < 32; ++jj) s1 += o[jj];
    s1 += __shfl_xor_sync(0xffffffffu, s1, 1);
    s1 += __shfl_xor_sync(0xffffffffu, s1, 2);
    float mean = s1 * (1.f/128.f);
    float s2 = 0.f;
#pragma unroll
    for (int jj = 0; jj < 32; ++jj) { float dv = o[jj] - mean; s2 = fmaf(dv, dv, s2); }
    s2 += __shfl_xor_sync(0xffffffffu, s2, 1);
    s2 += __shfl_xor_sync(0xffffffffu, s2, 2);
    float rstd = rsqrtf(s2 * (1.f/128.f) + LN_EPS);
    const int m = m0 + t;
    const float* gpp = g_gp + (size_t)m*D_ + h*DV + qq*32;
    float*       yp  = g_y  + (size_t)m*D_ + h*DV + qq*32;
#pragma unroll
    for (int jj = 0; jj < 32; ++jj) {
        float gv = gpp[jj];
        float si = gv / (1.f + __expf(-gv));
        yp[jj] = __uint_as_float(f2tf(si * ((o[jj] - mean) * rstd)));
    }
}

// ---------------- host driver -------------------------------------------------
extern "C" void kernel_launch(void* const* d_in, const int* in_sizes, int n_in,
                              void* d_out, int out_size)
{
    const float* x    = (const float*)d_in[0];
    const float* Wq   = (const float*)d_in[1];
    const float* Wk   = (const float*)d_in[2];
    const float* Wkg1 = (const float*)d_in[3];
    const float* Wkg2 = (const float*)d_in[4];
    const float* bkg2 = (const float*)d_in[5];
    const float* Wv   = (const float*)d_in[6];
    const float* Wg   = (const float*)d_in[7];
    const float* bg   = (const float*)d_in[8];
    const float* Wo   = (const float*)d_in[9];
    float* out = (float*)d_out;

    float *pq, *pk, *pv, *pgp, *pkg1, *py, *px, *pw;
    cudaGetSymbolAddress((void**)&pq,   g_q);
    cudaGetSymbolAddress((void**)&pk,   g_k);
    cudaGetSymbolAddress((void**)&pv,   g_v);
    cudaGetSymbolAddress((void**)&pgp,  g_gp);
    cudaGetSymbolAddress((void**)&pkg1, g_kg1);
    cudaGetSymbolAddress((void**)&py,   g_y);
    cudaGetSymbolAddress((void**)&px,   g_x);
    cudaGetSymbolAddress((void**)&pw,   g_w);

    cudaFuncSetAttribute(tf32_gemm_multi, cudaFuncAttributeMaxDynamicSharedMemorySize, GEMM_SMEM_BYTES);
    cudaFuncSetAttribute(state_kernel,    cudaFuncAttributeMaxDynamicSharedMemorySize, STATE_SMEM);
    cudaFuncSetAttribute(output_kernel,   cudaFuncAttributeMaxDynamicSharedMemorySize, OUT_SMEM);

    // single fused tf32 rounding launch (x + all weights)
    rnd_all_kernel<<<dim3((M_*D_/4 + 255)/256, 6), 256>>>(
        (const float4*)x, (const float4*)Wq, (const float4*)Wk,
        (const float4*)Wv, (const float4*)Wg, (const float4*)Wo,
        (float4*)px, (float4*)pw);

    // merged projection GEMMs: tiles [0,8)=Wq, [8,16)=Wk, [16,32)=Wv, [32,48)=Wg
    tf32_gemm_multi<<<dim3(48, M_/BM), GTHR, GEMM_SMEM_BYTES>>>(
        px, pw + WOFF_Q, pw + WOFF_K, pw + WOFF_V, pw + WOFF_G, bg,
        pq, pk, pv, pgp,
        D_,
        8, 16, 32,
        0, 0, 0,
        NQK, NQK, D_, D_,
        1.f, SCALE_QK, 1.f, 1.f);
    kg1_kernel<<<M_/16, 256>>>(x, Wkg1, pkg1);
    gate_kernel<<<M_, 256>>>(Wkg2, bkg2);

    // gate cumsum + q/k transform (parallel), then recurrence
    prep_kernel<<<dim3(NCHUNK, B_*H_), 64>>>();
    state_kernel<<<dim3(4, B_*H_), 128, STATE_SMEM>>>();
    output_kernel<<<dim3(NCHUNK, B_*H_), 256, OUT_SMEM>>>();

    // out = y @ Wo^T; tiles [8,16) read Wo rows 1024.. via pre-offset pointer
    tf32_gemm_multi<<<dim3(16, M_/BM), GTHR, GEMM_SMEM_BYTES>>>(
        py, pw + WOFF_O, pw + WOFF_O + (size_t)1024 * D_, pw + WOFF_O, pw + WOFF_O, nullptr,
        out, out, out, out,
        D_,
        8, 999, 999,
        1024, 0, 0,
        D_, D_, D_, D_,
        1.f, 1.f, 1.f, 1.f);
}

// round 13
// speedup vs baseline: 1.5719x; 1.5719x over previous
#include <cuda_runtime.h>
#include <cuda_fp16.h>
#include <cstdint>
#include <math.h>

// Problem dims (fixed)
#define B_      2
#define L_      2048
#define D_      2048
#define M_      4096          // B*L
#define H_      16
#define DK      64
#define DV      128
#define NQK     1024          // H*DK
#define CHUNK   64
#define NCHUNK  32            // L / CHUNK
#define SCALE_QK 0.08838834764831845f   // 128^-0.5
#define INV_NORM 0.0625f                 // 1/16
#define LN_EPS   1e-5f

// ---------------- scratch (static device globals; no allocation) -------------
__device__ float  g_q   [(size_t)M_ * NQK];   // after prep: q * e^G
__device__ float  g_k   [(size_t)M_ * NQK];   // after prep: k * e^-G (pre-scaled)
__device__ float  g_gate[(size_t)M_ * NQK];
__device__ float  g_kg1 [(size_t)M_ * 16];
__device__ float  g_v   [(size_t)M_ * D_];
__device__ float  g_gp  [(size_t)M_ * D_];
__device__ __half g_yh  [(size_t)M_ * D_];    // fp16 y for final GEMM
__device__ float  g_S   [(size_t)B_ * H_ * NCHUNK * DK * DV];
__device__ float  g_E   [(size_t)B_ * H_ * NCHUNK * DK];      // per-chunk decay
__device__ __half g_xh  [(size_t)M_ * D_];    // fp16 x
__device__ __half g_wh  [(size_t)8192 * D_];  // fp16 Wq|Wk|Wv|Wg|Wo

#define WOFF_Q  0
#define WOFF_K  ((size_t)1024 * D_)
#define WOFF_V  ((size_t)2048 * D_)
#define WOFF_G  ((size_t)4096 * D_)
#define WOFF_O  ((size_t)6144 * D_)

// ======================= PTX helpers (non-'a' features only) ==================
__device__ __forceinline__ uint32_t smem_u32(const void* p) {
    uint32_t a;
    asm("{ .reg .u64 t; cvta.to.shared.u64 t, %1; cvt.u32.u64 %0, t; }" : "=r"(a) : "l"(p));
    return a;
}
__device__ __forceinline__ void cp_async16(uint32_t dst, const void* src) {
    asm volatile("cp.async.cg.shared.global [%0], [%1], 16;" :: "r"(dst), "l"(src) : "memory");
}
#define CP_COMMIT() asm volatile("cp.async.commit_group;" ::: "memory")
#define CP_WAIT(N)  asm volatile("cp.async.wait_group %0;" :: "n"(N) : "memory")

__device__ __forceinline__ uint32_t f2tf(float f) {
    uint32_t u;
    asm("cvt.rna.tf32.f32 %0, %1;" : "=r"(u) : "f"(f));
    return u;
}
// fp16 MMA m16n8k16, fp32 accumulate (sm_80 baseline — no 'a' features)
__device__ __forceinline__ void mma_f16(float c[4], const uint32_t a[4], const uint32_t b[2]) {
    asm volatile(
        "mma.sync.aligned.m16n8k16.row.col.f32.f16.f16.f32 "
        "{%0,%1,%2,%3}, {%4,%5,%6,%7}, {%8,%9}, {%0,%1,%2,%3};"
        : "+f"(c[0]), "+f"(c[1]), "+f"(c[2]), "+f"(c[3])
        : "r"(a[0]), "r"(a[1]), "r"(a[2]), "r"(a[3]), "r"(b[0]), "r"(b[1]));
}

// ---------------- fused fp16 convert pass (segmented) -------------------------
// Each thread converts 8 floats -> 8 halves (16B store).
__global__ __launch_bounds__(256) void cvt_all_kernel(
    const float4* __restrict__ x,
    const float4* __restrict__ Wq, const float4* __restrict__ Wk,
    const float4* __restrict__ Wv, const float4* __restrict__ Wg,
    const float4* __restrict__ Wo,
    __half* __restrict__ dx, __half* __restrict__ dw)
{
    const int seg = blockIdx.y;
    const float4* src;
    __half* dst;
    int n8;
    switch (seg) {
        case 0: src = x;  dst = dx;            n8 = M_*D_/8;   break;
        case 1: src = Wq; dst = dw + WOFF_Q;   n8 = 1024*D_/8; break;
        case 2: src = Wk; dst = dw + WOFF_K;   n8 = 1024*D_/8; break;
        case 3: src = Wv; dst = dw + WOFF_V;   n8 = 2048*D_/8; break;
        case 4: src = Wg; dst = dw + WOFF_G;   n8 = 2048*D_/8; break;
        default:src = Wo; dst = dw + WOFF_O;   n8 = 2048*D_/8; break;
    }
    int i = blockIdx.x * blockDim.x + threadIdx.x;
    if (i < n8) {
        float4 v0 = src[2*i], v1 = src[2*i+1];
        __half2 h0 = __floats2half2_rn(v0.x, v0.y);
        __half2 h1 = __floats2half2_rn(v0.z, v0.w);
        __half2 h2 = __floats2half2_rn(v1.x, v1.y);
        __half2 h3 = __floats2half2_rn(v1.z, v1.w);
        uint4 u;
        u.x = *(uint32_t*)&h0; u.y = *(uint32_t*)&h1;
        u.z = *(uint32_t*)&h2; u.w = *(uint32_t*)&h3;
        *(uint4*)(dst + (size_t)i*8) = u;
    }
}

// ======================= fp16 GEMM (mma.sync m16n8k16), multi-target ==========
// A [M,K] row-major fp16, W [.,K] row-major fp16 selected by tile routing
// (W rows tile-local; callers pre-offset for col ranges of one matrix).
// C = alpha*A@W^T (+bias), fp32 out. Tile 128x128x64, 8 warps (2x4),
// warp tile 64x32 (4x4 m16n8k16). cp.async double-buffered.
#define BM 128
#define BN 128
#define BK 64                              // halves per K-tile
#define PITCH32 36                         // u32 per smem row (32 data + 4 pad)
#define TSTRIDE32 (128*PITCH32)            // u32 per tile stage
#define GEMM_SMEM_BYTES (4*TSTRIDE32*4)    // A[2] + B[2] = 73728

__global__ __launch_bounds__(256, 2)
void f16_gemm_multi(
    const __half* __restrict__ A,
    const __half* __restrict__ W0, const __half* __restrict__ W1,
    const __half* __restrict__ W2, const __half* __restrict__ W3,
    const float* __restrict__ bias3,
    float* __restrict__ C0, float* __restrict__ C1,
    float* __restrict__ C2, float* __restrict__ C3,
    int K,
    int s1, int s2, int s3,
    int cb1, int cb2, int cb3,
    int N0, int N1, int N2, int N3,
    float a0, float a1, float a2, float a3)
{
    extern __shared__ uint32_t smu[];
    uint32_t* Asm = smu;
    uint32_t* Bsm = smu + 2*TSTRIDE32;
    const uint32_t Abase_s = smem_u32(Asm);
    const uint32_t Bbase_s = smem_u32(Bsm);

    const int c = blockIdx.x;
    const int sel = (c >= s3) ? 3 : (c >= s2) ? 2 : (c >= s1) ? 1 : 0;
    const __half* W = (sel == 0) ? W0 : (sel == 1) ? W1 : (sel == 2) ? W2 : W3;
    float*        C = (sel == 0) ? C0 : (sel == 1) ? C1 : (sel == 2) ? C2 : C3;
    const int start   = (sel == 0) ? 0 : (sel == 1) ? s1 : (sel == 2) ? s2 : s3;
    const int colbase = (sel == 0) ? 0 : (sel == 1) ? cb1 : (sel == 2) ? cb2 : cb3;
    const int N       = (sel == 0) ? N0 : (sel == 1) ? N1 : (sel == 2) ? N2 : N3;
    const float alpha = (sel == 0) ? a0 : (sel == 1) ? a1 : (sel == 2) ? a2 : a3;
    const float* bias = (sel == 3) ? bias3 : nullptr;

    const int tid = threadIdx.x;
    const int wid = tid >> 5;
    const int lane = tid & 31;
    const int g  = lane >> 2;        // 0..7
    const int t4 = lane & 3;         // 0..3
    const int wm = wid >> 2;         // 0..1 -> 64-row block
    const int wn = wid & 3;          // 0..3 -> 32-col block
    const int m0 = blockIdx.y * BM;
    const int wrow = (c - start) * BN;   // tile-local row offset in W
    const int n0g = wrow + colbase;      // global output column base

    const __half* Ag = A + (size_t)m0   * K;
    const __half* Bg = W + (size_t)wrow * K;

    float cacc[4][4][4];
#pragma unroll
    for (int i = 0; i < 4; ++i)
#pragma unroll
        for (int j = 0; j < 4; ++j)
#pragma unroll
            for (int e = 0; e < 4; ++e) cacc[i][j][e] = 0.f;

    const int niter = K / BK;

    auto load_tile = [&](int kt, int s) {
        const int k0 = kt * BK;                 // in halves
        const uint32_t sa = Abase_s + (uint32_t)s * TSTRIDE32 * 4;
        const uint32_t sb = Bbase_s + (uint32_t)s * TSTRIDE32 * 4;
#pragma unroll
        for (int i = 0; i < 4; ++i) {           // A: 128 rows x 64 halves (128B)
            int idx = tid + 256*i;              // 0..1023
            int r = idx >> 3, sg = idx & 7;     // 8 x 16B per row
            cp_async16(sa + (uint32_t)(r*PITCH32 + sg*4)*4, Ag + (size_t)r*K + k0 + sg*8);
        }
#pragma unroll
        for (int i = 0; i < 4; ++i) {           // B: 128 rows x 64 halves
            int idx = tid + 256*i;
            int r = idx >> 3, sg = idx & 7;
            cp_async16(sb + (uint32_t)(r*PITCH32 + sg*4)*4, Bg + (size_t)r*K + k0 + sg*8);
        }
    };

    load_tile(0, 0);
    CP_COMMIT();

    for (int kt = 0; kt < niter; ++kt) {
        const int s = kt & 1;
        if (kt + 1 < niter) {
            load_tile(kt + 1, s ^ 1);
            CP_COMMIT();
            CP_WAIT(1);
        } else {
            CP_WAIT(0);
        }
        __syncthreads();

        const uint32_t* As = Asm + s * TSTRIDE32;
        const uint32_t* Bs = Bsm + s * TSTRIDE32;
#pragma unroll
        for (int kk = 0; kk < 4; ++kk) {        // 4 k-steps of K=16 halves (8 u32)
            uint32_t af[4][4];
#pragma unroll
            for (int mt = 0; mt < 4; ++mt) {
                const int r0 = wm*64 + mt*16 + g;
                const uint32_t* pa = As + kk*8 + t4;
                af[mt][0] = pa[(r0    )*PITCH32    ];
                af[mt][1] = pa[(r0 + 8)*PITCH32    ];
                af[mt][2] = pa[(r0    )*PITCH32 + 4];
                af[mt][3] = pa[(r0 + 8)*PITCH32 + 4];
            }
            uint32_t bf[4][2];
#pragma unroll
            for (int nt = 0; nt < 4; ++nt) {
                const int nr = wn*32 + nt*8 + g;
                const uint32_t* pb = Bs + (size_t)nr*PITCH32 + kk*8 + t4;
                bf[nt][0] = pb[0];
                bf[nt][1] = pb[4];
            }
#pragma unroll
            for (int mt = 0; mt < 4; ++mt)
#pragma unroll
                for (int nt = 0; nt < 4; ++nt)
                    mma_f16(cacc[mt][nt], af[mt], bf[nt]);
        }
        __syncthreads();
    }

#pragma unroll
    for (int mt = 0; mt < 4; ++mt) {
#pragma unroll
        for (int nt = 0; nt < 4; ++nt) {
            const int col = n0g + wn*32 + nt*8 + 2*t4;
            float b0 = bias ? __ldg(bias + col)     : 0.f;
            float b1 = bias ? __ldg(bias + col + 1) : 0.f;
            const int r0 = m0 + wm*64 + mt*16 + g;
            float2 v0 = make_float2(cacc[mt][nt][0]*alpha + b0, cacc[mt][nt][1]*alpha + b1);
            float2 v1 = make_float2(cacc[mt][nt][2]*alpha + b0, cacc[mt][nt][3]*alpha + b1);
            *(float2*)(C + (size_t)r0      * N + col) = v0;
            *(float2*)(C + (size_t)(r0+8)  * N + col) = v1;
        }
    }
}

// ---------------- kg1 = x @ Wkg1^T  ------------------------------------------
__global__ __launch_bounds__(256) void kg1_kernel(
    const float* __restrict__ x, const float* __restrict__ Wkg1,
    float* __restrict__ out)
{
    __shared__ float xs[16][68];
    __shared__ float ws[16][68];
    const int tid = threadIdx.x;
    const int tx = tid & 15;
    const int ty = tid >> 4;
    const int m0 = blockIdx.x * 16;
    const int lrow = tid >> 4;
    const int lcol = (tid & 15) * 4;
    float acc = 0.f;
    for (int kt = 0; kt < D_; kt += 64) {
        float4 xv = *(const float4*)(x    + (size_t)(m0 + lrow)*D_ + kt + lcol);
        float4 wv = *(const float4*)(Wkg1 + (size_t)lrow*D_        + kt + lcol);
        *(float4*)&xs[lrow][lcol] = xv;
        *(float4*)&ws[lrow][lcol] = wv;
        __syncthreads();
#pragma unroll
        for (int kk = 0; kk < 64; ++kk)
            acc = fmaf(xs[ty][kk], ws[tx][kk], acc);
        __syncthreads();
    }
    out[(size_t)(m0 + ty)*16 + tx] = acc;
}

// ---------------- gate = log_sigmoid(kg1 @ Wkg2^T + bkg2) / 16 ---------------
__global__ __launch_bounds__(256) void gate_kernel(
    const float* __restrict__ Wkg2, const float* __restrict__ bkg2)
{
    __shared__ float row[16];
    const int tid = threadIdx.x;
    const int m = blockIdx.x;
    if (tid < 16) row[tid] = g_kg1[(size_t)m*16 + tid];
    __syncthreads();
#pragma unroll
    for (int i = 0; i < 4; ++i) {
        int n = i*256 + tid;
        const float4* wp = (const float4*)(Wkg2 + (size_t)n*16);
        float4 w0 = wp[0], w1 = wp[1], w2 = wp[2], w3 = wp[3];
        float acc = bkg2[n];
        acc += row[0]*w0.x + row[1]*w0.y + row[2]*w0.z + row[3]*w0.w;
        acc += row[4]*w1.x + row[5]*w1.y + row[6]*w1.z + row[7]*w1.w;
        acc += row[8]*w2.x + row[9]*w2.y + row[10]*w2.z + row[11]*w2.w;
        acc += row[12]*w3.x + row[13]*w3.y + row[14]*w3.z + row[15]*w3.w;
        float z = acc;
        float e  = __expf(-fabsf(z));
        float ls = fminf(z, 0.f) - __logf(1.f + e);
        g_gate[(size_t)m*NQK + n] = ls * INV_NORM;
    }
}

// ---------------- prep: cumsum gates, transform q/k in place, store E --------
__global__ __launch_bounds__(64) void prep_kernel()
{
    const int c  = blockIdx.x;
    const int bh = blockIdx.y;
    const int b = bh >> 4, h = bh & 15;
    const int d = threadIdx.x;
    const int m0 = b * L_ + c * CHUNK;
    size_t gi = (size_t)m0 * NQK + h * DK + d;
    float run = 0.f;
    for (int t = 0; t < CHUNK; ++t) {
        run += g_gate[gi];
        float eg = __expf(run);
        float en = __expf(-run);
        g_q[gi] *= eg;
        g_k[gi] *= en;
        gi += NQK;
    }
    g_E[(size_t)(bh * NCHUNK + c) * DK + d] = __expf(run);
}

// ---------------- pass 1: chunk states, cp.async pipelined -------------------
#define SKP_K 68
#define SKP_V 36
#define STATE_SMEM ((2*64*SKP_K + 2*64*SKP_V)*4)

__global__ __launch_bounds__(128) void state_kernel()
{
    extern __shared__ float sms[];
    float* khs = sms;                    // [2][64][SKP_K]
    float* vvs = sms + 2*64*SKP_K;       // [2][64][SKP_V]
    const uint32_t kh_s = smem_u32(khs);
    const uint32_t vv_s = smem_u32(vvs);

    const int bq = blockIdx.x;
    const int bh = blockIdx.y;
    const int b = bh >> 4, h = bh & 15;
    const int tid = threadIdx.x;
    const int ty = tid >> 3;
    const int tx = tid & 7;
    const int mb = b * L_;

    auto prefetch = [&](int c, int s) {
        const int m0 = mb + c * CHUNK;
        const uint32_t ka = kh_s + (uint32_t)s * 64*SKP_K*4;
        const uint32_t va = vv_s + (uint32_t)s * 64*SKP_V*4;
#pragma unroll
        for (int i = 0; i < 8; ++i) {
            int e = tid + 128*i;
            int t = e >> 4, q4 = (e & 15) * 4;
            cp_async16(ka + (uint32_t)(t*SKP_K + q4)*4,
                       g_k + (size_t)(m0 + t)*NQK + h*DK + q4);
        }
#pragma unroll
        for (int i = 0; i < 4; ++i) {
            int e = tid + 128*i;
            int t = e >> 3, q4 = (e & 7) * 4;
            cp_async16(va + (uint32_t)(t*SKP_V + q4)*4,
                       g_v + (size_t)(m0 + t)*D_ + h*DV + bq*32 + q4);
        }
    };

    float S[4][4];
#pragma unroll
    for (int dd = 0; dd < 4; ++dd)
#pragma unroll
        for (int jj = 0; jj < 4; ++jj) S[dd][jj] = 0.f;

    prefetch(0, 0);
    CP_COMMIT();

    for (int c = 0; c < NCHUNK; ++c) {
        const int s = c & 1;
        CP_WAIT(0);
        __syncthreads();
        if (c + 1 < NCHUNK) {
            prefetch(c + 1, s ^ 1);
            CP_COMMIT();
        }

        float* sp = g_S + (size_t)(bh * NCHUNK + c) * (DK * DV) + (size_t)bq * 32;
#pragma unroll
        for (int dd = 0; dd < 4; ++dd)
            *(float4*)(sp + (size_t)(ty*4 + dd)*DV + tx*4) =
                make_float4(S[dd][0], S[dd][1], S[dd][2], S[dd][3]);

        float acc[4][4];
#pragma unroll
        for (int dd = 0; dd < 4; ++dd)
#pragma unroll
            for (int jj = 0; jj < 4; ++jj) acc[dd][jj] = 0.f;

        const float* kb = khs + s * 64*SKP_K;
        const float* vb = vvs + s * 64*SKP_V;
        for (int t = 0; t < CHUNK; ++t) {
            float4 kv = *(const float4*)(kb + t*SKP_K + ty*4);
            float4 vv4 = *(const float4*)(vb + t*SKP_V + tx*4);
            float ka[4] = {kv.x, kv.y, kv.z, kv.w};
            float va[4] = {vv4.x, vv4.y, vv4.z, vv4.w};
#pragma unroll
            for (int dd = 0; dd < 4; ++dd)
#pragma unroll
                for (int jj = 0; jj < 4; ++jj)
                    acc[dd][jj] = fmaf(ka[dd], va[jj], acc[dd][jj]);
        }

        const float* ep = g_E + (size_t)(bh * NCHUNK + c) * DK + ty*4;
        float E[4] = {ep[0], ep[1], ep[2], ep[3]};
#pragma unroll
        for (int dd = 0; dd < 4; ++dd)
#pragma unroll
            for (int jj = 0; jj < 4; ++jj)
                S[dd][jj] = E[dd] * (S[dd][jj] + acc[dd][jj]);
    }
}

// ---------------- pass 2: chunk outputs + LN + SiLU gating --------------------
#define OUT_SMEM ((2*64*68 + 64*65 + 64*132)*4)

__global__ __launch_bounds__(256) void output_kernel()
{
    extern __shared__ float sm[];
    float (*qs)[68]  = (float(*)[68]) sm;
    float (*ks)[68]  = (float(*)[68])(sm + 64*68);
    float (*GA)[65]  = (float(*)[65])(sm + 2*64*68);
    float (*buf)[132]= (float(*)[132])(sm + 2*64*68 + 64*65);   // Sp, then V

    const int c  = blockIdx.x;
    const int bh = blockIdx.y;
    const int b = bh >> 4, h = bh & 15;
    const int tid = threadIdx.x;
    const int m0 = b * L_ + c * CHUNK;
    const size_t sbase = (size_t)(bh * NCHUNK + c) * (DK * DV);

    for (int e = tid; e < CHUNK*DK; e += 256) {
        int t = e >> 6, d = e & 63;
        size_t gi = (size_t)(m0 + t)*NQK + h*DK + d;
        qs[t][d] = g_q[gi];
        ks[t][d] = g_k[gi];
    }
    for (int e = tid; e < DK*DV; e += 256) {
        int t = e >> 7, j = e & 127;
        buf[t][j] = g_S[sbase + e];
    }
    __syncthreads();

    for (int e = tid; e < CHUNK*CHUNK; e += 256) {
        int t = e >> 6, s = e & 63;
        float acc = 0.f;
        if (s <= t) {
            const float4* qp = (const float4*)&qs[t][0];
            const float4* kp = (const float4*)&ks[s][0];
#pragma unroll
            for (int d4 = 0; d4 < 16; ++d4) {
                float4 qa = qp[d4], kk4 = kp[d4];
                acc = fmaf(qa.x, kk4.x, acc);
                acc = fmaf(qa.y, kk4.y, acc);
                acc = fmaf(qa.z, kk4.z, acc);
                acc = fmaf(qa.w, kk4.w, acc);
            }
        }
        GA[t][s] = acc;
    }

    const int t  = tid >> 2;
    const int qq = tid & 3;
    float o[32];
#pragma unroll
    for (int jj = 0; jj < 32; ++jj) o[jj] = 0.f;

    for (int d = 0; d < DK; ++d) {
        float qv = qs[t][d];
        const float4* sp4 = (const float4*)&buf[d][qq*32];
#pragma unroll
        for (int j4 = 0; j4 < 8; ++j4) {
            float4 vv = sp4[j4];
            o[j4*4+0] = fmaf(qv, vv.x, o[j4*4+0]);
            o[j4*4+1] = fmaf(qv, vv.y, o[j4*4+1]);
            o[j4*4+2] = fmaf(qv, vv.z, o[j4*4+2]);
            o[j4*4+3] = fmaf(qv, vv.w, o[j4*4+3]);
        }
    }
    __syncthreads();
    for (int e = tid; e < CHUNK*DV; e += 256) {
        int s = e >> 7, j = e & 127;
        buf[s][j] = g_v[(size_t)(m0 + s)*D_ + h*DV + j];
    }
    __syncthreads();
    for (int s = 0; s <= t; ++s) {
        float av = GA[t][s];
        const float4* vp4 = (const float4*)&buf[s][qq*32];
#pragma unroll
        for (int j4 = 0; j4 < 8; ++j4) {
            float4 vv = vp4[j4];
            o[j4*4+0] = fmaf(av, vv.x, o[j4*4+0]);
            o[j4*4+1] = fmaf(av, vv.y, o[j4*4+1]);
            o[j4*4+2] = fmaf(av, vv.z, o[j4*4+2]);
            o[j4*4+3] = fmaf(av, vv.w, o[j4*4+3]);
        }
    }

    float s1 = 0.f;
#pragma unroll
    for (int jj = 0; jj < 32; ++jj) s1 += o[jj];
    s1 += __shfl_xor_sync(0xffffffffu, s1, 1);
    s1 += __shfl_xor_sync(0xffffffffu, s1, 2);
    float mean = s1 * (1.f/128.f);
    float s2 = 0.f;
#pragma unroll
    for (int jj = 0; jj < 32; ++jj) { float dv = o[jj] - mean; s2 = fmaf(dv, dv, s2); }
    s2 += __shfl_xor_sync(0xffffffffu, s2, 1);
    s2 += __shfl_xor_sync(0xffffffffu, s2, 2);
    float rstd = rsqrtf(s2 * (1.f/128.f) + LN_EPS);
    const int m = m0 + t;
    const float* gpp = g_gp + (size_t)m*D_ + h*DV + qq*32;
    __half*      yp  = g_yh + (size_t)m*D_ + h*DV + qq*32;
#pragma unroll
    for (int jj = 0; jj < 32; ++jj) {
        float gv = gpp[jj];
        float si = gv / (1.f + __expf(-gv));
        yp[jj] = __float2half_rn(si * ((o[jj] - mean) * rstd));
    }
}

// ---------------- host driver -------------------------------------------------
extern "C" void kernel_launch(void* const* d_in, const int* in_sizes, int n_in,
                              void* d_out, int out_size)
{
    const float* x    = (const float*)d_in[0];
    const float* Wq   = (const float*)d_in[1];
    const float* Wk   = (const float*)d_in[2];
    const float* Wkg1 = (const float*)d_in[3];
    const float* Wkg2 = (const float*)d_in[4];
    const float* bkg2 = (const float*)d_in[5];
    const float* Wv   = (const float*)d_in[6];
    const float* Wg   = (const float*)d_in[7];
    const float* bg   = (const float*)d_in[8];
    const float* Wo   = (const float*)d_in[9];
    float* out = (float*)d_out;

    float *pq, *pk, *pv, *pgp, *pkg1;
    __half *pyh, *pxh, *pwh;
    cudaGetSymbolAddress((void**)&pq,   g_q);
    cudaGetSymbolAddress((void**)&pk,   g_k);
    cudaGetSymbolAddress((void**)&pv,   g_v);
    cudaGetSymbolAddress((void**)&pgp,  g_gp);
    cudaGetSymbolAddress((void**)&pkg1, g_kg1);
    cudaGetSymbolAddress((void**)&pyh,  g_yh);
    cudaGetSymbolAddress((void**)&pxh,  g_xh);
    cudaGetSymbolAddress((void**)&pwh,  g_wh);

    cudaFuncSetAttribute(f16_gemm_multi, cudaFuncAttributeMaxDynamicSharedMemorySize, GEMM_SMEM_BYTES);
    cudaFuncSetAttribute(state_kernel,   cudaFuncAttributeMaxDynamicSharedMemorySize, STATE_SMEM);
    cudaFuncSetAttribute(output_kernel,  cudaFuncAttributeMaxDynamicSharedMemorySize, OUT_SMEM);

    // single fused fp16 convert launch (x + all weights)
    cvt_all_kernel<<<dim3((M_*D_/8 + 255)/256, 6), 256>>>(
        (const float4*)x, (const float4*)Wq, (const float4*)Wk,
        (const float4*)Wv, (const float4*)Wg, (const float4*)Wo,
        pxh, pwh);

    // merged projection GEMMs: tiles [0,8)=Wq, [8,16)=Wk, [16,32)=Wv, [32,48)=Wg
    f16_gemm_multi<<<dim3(48, M_/BM), 256, GEMM_SMEM_BYTES>>>(
        pxh, pwh + WOFF_Q, pwh + WOFF_K, pwh + WOFF_V, pwh + WOFF_G, bg,
        pq, pk, pv, pgp,
        D_,
        8, 16, 32,
        0, 0, 0,
        NQK, NQK, D_, D_,
        1.f, SCALE_QK, 1.f, 1.f);
    kg1_kernel<<<M_/16, 256>>>(x, Wkg1, pkg1);
    gate_kernel<<<M_, 256>>>(Wkg2, bkg2);

    // gate cumsum + q/k transform (parallel), then recurrence
    prep_kernel<<<dim3(NCHUNK, B_*H_), 64>>>();
    state_kernel<<<dim3(4, B_*H_), 128, STATE_SMEM>>>();
    output_kernel<<<dim3(NCHUNK, B_*H_), 256, OUT_SMEM>>>();

    // out = y @ Wo^T; tiles [8,16) read Wo rows 1024.. via pre-offset pointer
    f16_gemm_multi<<<dim3(16, M_/BM), 256, GEMM_SMEM_BYTES>>>(
        pyh, pwh + WOFF_O, pwh + WOFF_O + (size_t)1024 * D_, pwh + WOFF_O, pwh + WOFF_O, nullptr,
        out, out, out, out,
        D_,
        8, 999, 999,
        1024, 0, 0,
        D_, D_, D_, D_,
        1.f, 1.f, 1.f, 1.f);
}

// round 14
// speedup vs baseline: 1.5953x; 1.0149x over previous
#include <cuda_runtime.h>
#include <cuda_fp16.h>
#include <cstdint>
#include <math.h>

// Problem dims (fixed)
#define B_      2
#define L_      2048
#define D_      2048
#define M_      4096          // B*L
#define H_      16
#define DK      64
#define DV      128
#define NQK     1024          // H*DK
#define CHUNK   64
#define NCHUNK  32            // L / CHUNK
#define SCALE_QK 0.08838834764831845f   // 128^-0.5
#define INV_NORM 0.0625f                 // 1/16
#define LN_EPS   1e-5f

// ---------------- scratch (static device globals; no allocation) -------------
__device__ float  g_q   [(size_t)M_ * NQK];   // after prep: q * e^G
__device__ float  g_k   [(size_t)M_ * NQK];   // after prep: k * e^-G (pre-scaled)
__device__ float  g_gate[(size_t)M_ * NQK];
__device__ float  g_kg1 [(size_t)M_ * 16];
__device__ float  g_v   [(size_t)M_ * D_];
__device__ float  g_gp  [(size_t)M_ * D_];
__device__ __half g_yh  [(size_t)M_ * D_];    // fp16 y for final GEMM
__device__ float  g_S   [(size_t)B_ * H_ * NCHUNK * DK * DV];
__device__ float  g_E   [(size_t)B_ * H_ * NCHUNK * DK];      // per-chunk decay
__device__ __half g_xh  [(size_t)M_ * D_];    // fp16 x
__device__ __half g_wh  [(size_t)8192 * D_];  // fp16 Wq|Wk|Wv|Wg|Wo

#define WOFF_Q  0
#define WOFF_K  ((size_t)1024 * D_)
#define WOFF_V  ((size_t)2048 * D_)
#define WOFF_G  ((size_t)4096 * D_)
#define WOFF_O  ((size_t)6144 * D_)

// ======================= PTX helpers (non-'a' features only) ==================
__device__ __forceinline__ uint32_t smem_u32(const void* p) {
    uint32_t a;
    asm("{ .reg .u64 t; cvta.to.shared.u64 t, %1; cvt.u32.u64 %0, t; }" : "=r"(a) : "l"(p));
    return a;
}
__device__ __forceinline__ void cp_async16(uint32_t dst, const void* src) {
    asm volatile("cp.async.cg.shared.global [%0], [%1], 16;" :: "r"(dst), "l"(src) : "memory");
}
#define CP_COMMIT() asm volatile("cp.async.commit_group;" ::: "memory")
#define CP_WAIT(N)  asm volatile("cp.async.wait_group %0;" :: "n"(N) : "memory")

// fp16 MMA m16n8k16, fp32 accumulate (sm_80 baseline)
__device__ __forceinline__ void mma_f16(float c[4], const uint32_t a[4], const uint32_t b[2]) {
    asm volatile(
        "mma.sync.aligned.m16n8k16.row.col.f32.f16.f16.f32 "
        "{%0,%1,%2,%3}, {%4,%5,%6,%7}, {%8,%9}, {%0,%1,%2,%3};"
        : "+f"(c[0]), "+f"(c[1]), "+f"(c[2]), "+f"(c[3])
        : "r"(a[0]), "r"(a[1]), "r"(a[2]), "r"(a[3]), "r"(b[0]), "r"(b[1]));
}
// warp-collective 4x 8x8 b16 matrix load
__device__ __forceinline__ void ldsm_x4(uint32_t r[4], uint32_t addr) {
    asm volatile("ldmatrix.sync.aligned.m8n8.x4.shared.b16 {%0,%1,%2,%3}, [%4];"
        : "=r"(r[0]), "=r"(r[1]), "=r"(r[2]), "=r"(r[3]) : "r"(addr));
}

// ---------------- fused fp16 convert pass (segmented) -------------------------
__global__ __launch_bounds__(256) void cvt_all_kernel(
    const float4* __restrict__ x,
    const float4* __restrict__ Wq, const float4* __restrict__ Wk,
    const float4* __restrict__ Wv, const float4* __restrict__ Wg,
    const float4* __restrict__ Wo,
    __half* __restrict__ dx, __half* __restrict__ dw)
{
    const int seg = blockIdx.y;
    const float4* src;
    __half* dst;
    int n8;
    switch (seg) {
        case 0: src = x;  dst = dx;            n8 = M_*D_/8;   break;
        case 1: src = Wq; dst = dw + WOFF_Q;   n8 = 1024*D_/8; break;
        case 2: src = Wk; dst = dw + WOFF_K;   n8 = 1024*D_/8; break;
        case 3: src = Wv; dst = dw + WOFF_V;   n8 = 2048*D_/8; break;
        case 4: src = Wg; dst = dw + WOFF_G;   n8 = 2048*D_/8; break;
        default:src = Wo; dst = dw + WOFF_O;   n8 = 2048*D_/8; break;
    }
    int i = blockIdx.x * blockDim.x + threadIdx.x;
    if (i < n8) {
        float4 v0 = src[2*i], v1 = src[2*i+1];
        __half2 h0 = __floats2half2_rn(v0.x, v0.y);
        __half2 h1 = __floats2half2_rn(v0.z, v0.w);
        __half2 h2 = __floats2half2_rn(v1.x, v1.y);
        __half2 h3 = __floats2half2_rn(v1.z, v1.w);
        uint4 u;
        u.x = *(uint32_t*)&h0; u.y = *(uint32_t*)&h1;
        u.z = *(uint32_t*)&h2; u.w = *(uint32_t*)&h3;
        *(uint4*)(dst + (size_t)i*8) = u;
    }
}

// ======================= fp16 GEMM (mma.sync m16n8k16), multi-target ==========
// Tile 128x128x64, 8 warps (2x4), warp tile 64x32. cp.async double-buffered.
// Fragment loads via ldmatrix.x4 (6 LDSM per kk-step vs 24 LDS.32).
#define BM 128
#define BN 128
#define BK 64                              // halves per K-tile
#define PITCH32 36                         // u32 per smem row (32 data + 4 pad)
#define TSTRIDE32 (128*PITCH32)            // u32 per tile stage
#define GEMM_SMEM_BYTES (4*TSTRIDE32*4)    // A[2] + B[2] = 73728

__global__ __launch_bounds__(256, 2)
void f16_gemm_multi(
    const __half* __restrict__ A,
    const __half* __restrict__ W0, const __half* __restrict__ W1,
    const __half* __restrict__ W2, const __half* __restrict__ W3,
    const float* __restrict__ bias3,
    float* __restrict__ C0, float* __restrict__ C1,
    float* __restrict__ C2, float* __restrict__ C3,
    int K,
    int s1, int s2, int s3,
    int cb1, int cb2, int cb3,
    int N0, int N1, int N2, int N3,
    float a0, float a1, float a2, float a3)
{
    extern __shared__ uint32_t smu[];
    uint32_t* Asm = smu;
    uint32_t* Bsm = smu + 2*TSTRIDE32;
    const uint32_t Abase_s = smem_u32(Asm);
    const uint32_t Bbase_s = smem_u32(Bsm);

    const int c = blockIdx.x;
    const int sel = (c >= s3) ? 3 : (c >= s2) ? 2 : (c >= s1) ? 1 : 0;
    const __half* W = (sel == 0) ? W0 : (sel == 1) ? W1 : (sel == 2) ? W2 : W3;
    float*        C = (sel == 0) ? C0 : (sel == 1) ? C1 : (sel == 2) ? C2 : C3;
    const int start   = (sel == 0) ? 0 : (sel == 1) ? s1 : (sel == 2) ? s2 : s3;
    const int colbase = (sel == 0) ? 0 : (sel == 1) ? cb1 : (sel == 2) ? cb2 : cb3;
    const int N       = (sel == 0) ? N0 : (sel == 1) ? N1 : (sel == 2) ? N2 : N3;
    const float alpha = (sel == 0) ? a0 : (sel == 1) ? a1 : (sel == 2) ? a2 : a3;
    const float* bias = (sel == 3) ? bias3 : nullptr;

    const int tid = threadIdx.x;
    const int wid = tid >> 5;
    const int lane = tid & 31;
    const int g  = lane >> 2;        // 0..7
    const int t4 = lane & 3;         // 0..3
    const int wm = wid >> 2;         // 0..1 -> 64-row block
    const int wn = wid & 3;          // 0..3 -> 32-col block
    const int m0 = blockIdx.y * BM;
    const int wrow = (c - start) * BN;   // tile-local row offset in W
    const int n0g = wrow + colbase;      // global output column base

    // ldmatrix per-lane address components
    const int arow = (lane & 7) + ((lane >> 3) & 1) * 8;  // row within 16-row frag
    const int acol = ((lane >> 4) & 1) * 4;               // u32 col (k-half block)
    const int brow = lane & 7;                            // row within 8-row n-block
    const int bnts = (lane >> 4) & 1;                     // which nt within pair
    const int bcol = ((lane >> 3) & 1) * 4;               // u32 col (k-half block)

    const __half* Ag = A + (size_t)m0   * K;
    const __half* Bg = W + (size_t)wrow * K;

    float cacc[4][4][4];
#pragma unroll
    for (int i = 0; i < 4; ++i)
#pragma unroll
        for (int j = 0; j < 4; ++j)
#pragma unroll
            for (int e = 0; e < 4; ++e) cacc[i][j][e] = 0.f;

    const int niter = K / BK;

    auto load_tile = [&](int kt, int s) {
        const int k0 = kt * BK;                 // in halves
        const uint32_t sa = Abase_s + (uint32_t)s * TSTRIDE32 * 4;
        const uint32_t sb = Bbase_s + (uint32_t)s * TSTRIDE32 * 4;
#pragma unroll
        for (int i = 0; i < 4; ++i) {           // A: 128 rows x 64 halves (128B)
            int idx = tid + 256*i;              // 0..1023
            int r = idx >> 3, sg = idx & 7;     // 8 x 16B per row
            cp_async16(sa + (uint32_t)(r*PITCH32 + sg*4)*4, Ag + (size_t)r*K + k0 + sg*8);
        }
#pragma unroll
        for (int i = 0; i < 4; ++i) {           // B: 128 rows x 64 halves
            int idx = tid + 256*i;
            int r = idx >> 3, sg = idx & 7;
            cp_async16(sb + (uint32_t)(r*PITCH32 + sg*4)*4, Bg + (size_t)r*K + k0 + sg*8);
        }
    };

    load_tile(0, 0);
    CP_COMMIT();

    for (int kt = 0; kt < niter; ++kt) {
        const int s = kt & 1;
        if (kt + 1 < niter) {
            load_tile(kt + 1, s ^ 1);
            CP_COMMIT();
            CP_WAIT(1);
        } else {
            CP_WAIT(0);
        }
        __syncthreads();

        const uint32_t As_addr = Abase_s + (uint32_t)s * TSTRIDE32 * 4;
        const uint32_t Bs_addr = Bbase_s + (uint32_t)s * TSTRIDE32 * 4;
#pragma unroll
        for (int kk = 0; kk < 4; ++kk) {        // 4 k-steps of 16 halves (8 u32)
            uint32_t af[4][4];
#pragma unroll
            for (int mt = 0; mt < 4; ++mt) {
                uint32_t a_addr = As_addr +
                    (uint32_t)(((wm*64 + mt*16 + arow) * PITCH32) + kk*8 + acol) * 4;
                ldsm_x4(af[mt], a_addr);
            }
            uint32_t bf[4][2];
#pragma unroll
            for (int p = 0; p < 2; ++p) {
                uint32_t tmp[4];
                uint32_t b_addr = Bs_addr +
                    (uint32_t)(((wn*32 + (2*p + bnts)*8 + brow) * PITCH32) + kk*8 + bcol) * 4;
                ldsm_x4(tmp, b_addr);
                bf[2*p  ][0] = tmp[0]; bf[2*p  ][1] = tmp[1];
                bf[2*p+1][0] = tmp[2]; bf[2*p+1][1] = tmp[3];
            }
#pragma unroll
            for (int mt = 0; mt < 4; ++mt)
#pragma unroll
                for (int nt = 0; nt < 4; ++nt)
                    mma_f16(cacc[mt][nt], af[mt], bf[nt]);
        }
        __syncthreads();
    }

#pragma unroll
    for (int mt = 0; mt < 4; ++mt) {
#pragma unroll
        for (int nt = 0; nt < 4; ++nt) {
            const int col = n0g + wn*32 + nt*8 + 2*t4;
            float b0 = bias ? __ldg(bias + col)     : 0.f;
            float b1 = bias ? __ldg(bias + col + 1) : 0.f;
            const int r0 = m0 + wm*64 + mt*16 + g;
            float2 v0 = make_float2(cacc[mt][nt][0]*alpha + b0, cacc[mt][nt][1]*alpha + b1);
            float2 v1 = make_float2(cacc[mt][nt][2]*alpha + b0, cacc[mt][nt][3]*alpha + b1);
            *(float2*)(C + (size_t)r0      * N + col) = v0;
            *(float2*)(C + (size_t)(r0+8)  * N + col) = v1;
        }
    }
}

// ---------------- kg1 = x @ Wkg1^T  ------------------------------------------
__global__ __launch_bounds__(256) void kg1_kernel(
    const float* __restrict__ x, const float* __restrict__ Wkg1,
    float* __restrict__ out)
{
    __shared__ float xs[16][68];
    __shared__ float ws[16][68];
    const int tid = threadIdx.x;
    const int tx = tid & 15;
    const int ty = tid >> 4;
    const int m0 = blockIdx.x * 16;
    const int lrow = tid >> 4;
    const int lcol = (tid & 15) * 4;
    float acc = 0.f;
    for (int kt = 0; kt < D_; kt += 64) {
        float4 xv = *(const float4*)(x    + (size_t)(m0 + lrow)*D_ + kt + lcol);
        float4 wv = *(const float4*)(Wkg1 + (size_t)lrow*D_        + kt + lcol);
        *(float4*)&xs[lrow][lcol] = xv;
        *(float4*)&ws[lrow][lcol] = wv;
        __syncthreads();
#pragma unroll
        for (int kk = 0; kk < 64; ++kk)
            acc = fmaf(xs[ty][kk], ws[tx][kk], acc);
        __syncthreads();
    }
    out[(size_t)(m0 + ty)*16 + tx] = acc;
}

// ---------------- gate = log_sigmoid(kg1 @ Wkg2^T + bkg2) / 16 ---------------
__global__ __launch_bounds__(256) void gate_kernel(
    const float* __restrict__ Wkg2, const float* __restrict__ bkg2)
{
    __shared__ float row[16];
    const int tid = threadIdx.x;
    const int m = blockIdx.x;
    if (tid < 16) row[tid] = g_kg1[(size_t)m*16 + tid];
    __syncthreads();
#pragma unroll
    for (int i = 0; i < 4; ++i) {
        int n = i*256 + tid;
        const float4* wp = (const float4*)(Wkg2 + (size_t)n*16);
        float4 w0 = wp[0], w1 = wp[1], w2 = wp[2], w3 = wp[3];
        float acc = bkg2[n];
        acc += row[0]*w0.x + row[1]*w0.y + row[2]*w0.z + row[3]*w0.w;
        acc += row[4]*w1.x + row[5]*w1.y + row[6]*w1.z + row[7]*w1.w;
        acc += row[8]*w2.x + row[9]*w2.y + row[10]*w2.z + row[11]*w2.w;
        acc += row[12]*w3.x + row[13]*w3.y + row[14]*w3.z + row[15]*w3.w;
        float z = acc;
        float e  = __expf(-fabsf(z));
        float ls = fminf(z, 0.f) - __logf(1.f + e);
        g_gate[(size_t)m*NQK + n] = ls * INV_NORM;
    }
}

// ---------------- prep: cumsum gates, transform q/k in place, store E --------
__global__ __launch_bounds__(64) void prep_kernel()
{
    const int c  = blockIdx.x;
    const int bh = blockIdx.y;
    const int b = bh >> 4, h = bh & 15;
    const int d = threadIdx.x;
    const int m0 = b * L_ + c * CHUNK;
    size_t gi = (size_t)m0 * NQK + h * DK + d;
    float run = 0.f;
    for (int t = 0; t < CHUNK; ++t) {
        run += g_gate[gi];
        float eg = __expf(run);
        float en = __expf(-run);
        g_q[gi] *= eg;
        g_k[gi] *= en;
        gi += NQK;
    }
    g_E[(size_t)(bh * NCHUNK + c) * DK + d] = __expf(run);
}

// ---------------- pass 1: chunk states, cp.async pipelined -------------------
#define SKP_K 68
#define SKP_V 36
#define STATE_SMEM ((2*64*SKP_K + 2*64*SKP_V)*4)

__global__ __launch_bounds__(128) void state_kernel()
{
    extern __shared__ float sms[];
    float* khs = sms;                    // [2][64][SKP_K]
    float* vvs = sms + 2*64*SKP_K;       // [2][64][SKP_V]
    const uint32_t kh_s = smem_u32(khs);
    const uint32_t vv_s = smem_u32(vvs);

    const int bq = blockIdx.x;
    const int bh = blockIdx.y;
    const int b = bh >> 4, h = bh & 15;
    const int tid = threadIdx.x;
    const int ty = tid >> 3;
    const int tx = tid & 7;
    const int mb = b * L_;

    auto prefetch = [&](int c, int s) {
        const int m0 = mb + c * CHUNK;
        const uint32_t ka = kh_s + (uint32_t)s * 64*SKP_K*4;
        const uint32_t va = vv_s + (uint32_t)s * 64*SKP_V*4;
#pragma unroll
        for (int i = 0; i < 8; ++i) {
            int e = tid + 128*i;
            int t = e >> 4, q4 = (e & 15) * 4;
            cp_async16(ka + (uint32_t)(t*SKP_K + q4)*4,
                       g_k + (size_t)(m0 + t)*NQK + h*DK + q4);
        }
#pragma unroll
        for (int i = 0; i < 4; ++i) {
            int e = tid + 128*i;
            int t = e >> 3, q4 = (e & 7) * 4;
            cp_async16(va + (uint32_t)(t*SKP_V + q4)*4,
                       g_v + (size_t)(m0 + t)*D_ + h*DV + bq*32 + q4);
        }
    };

    float S[4][4];
#pragma unroll
    for (int dd = 0; dd < 4; ++dd)
#pragma unroll
        for (int jj = 0; jj < 4; ++jj) S[dd][jj] = 0.f;

    prefetch(0, 0);
    CP_COMMIT();

    for (int c = 0; c < NCHUNK; ++c) {
        const int s = c & 1;
        CP_WAIT(0);
        __syncthreads();
        if (c + 1 < NCHUNK) {
            prefetch(c + 1, s ^ 1);
            CP_COMMIT();
        }

        float* sp = g_S + (size_t)(bh * NCHUNK + c) * (DK * DV) + (size_t)bq * 32;
#pragma unroll
        for (int dd = 0; dd < 4; ++dd)
            *(float4*)(sp + (size_t)(ty*4 + dd)*DV + tx*4) =
                make_float4(S[dd][0], S[dd][1], S[dd][2], S[dd][3]);

        float acc[4][4];
#pragma unroll
        for (int dd = 0; dd < 4; ++dd)
#pragma unroll
            for (int jj = 0; jj < 4; ++jj) acc[dd][jj] = 0.f;

        const float* kb = khs + s * 64*SKP_K;
        const float* vb = vvs + s * 64*SKP_V;
        for (int t = 0; t < CHUNK; ++t) {
            float4 kv = *(const float4*)(kb + t*SKP_K + ty*4);
            float4 vv4 = *(const float4*)(vb + t*SKP_V + tx*4);
            float ka[4] = {kv.x, kv.y, kv.z, kv.w};
            float va[4] = {vv4.x, vv4.y, vv4.z, vv4.w};
#pragma unroll
            for (int dd = 0; dd < 4; ++dd)
#pragma unroll
                for (int jj = 0; jj < 4; ++jj)
                    acc[dd][jj] = fmaf(ka[dd], va[jj], acc[dd][jj]);
        }

        const float* ep = g_E + (size_t)(bh * NCHUNK + c) * DK + ty*4;
        float E[4] = {ep[0], ep[1], ep[2], ep[3]};
#pragma unroll
        for (int dd = 0; dd < 4; ++dd)
#pragma unroll
            for (int jj = 0; jj < 4; ++jj)
                S[dd][jj] = E[dd] * (S[dd][jj] + acc[dd][jj]);
    }
}

// ---------------- pass 2: chunk outputs + LN + SiLU gating --------------------
#define OUT_SMEM ((2*64*68 + 64*65 + 64*132)*4)

__global__ __launch_bounds__(256) void output_kernel()
{
    extern __shared__ float sm[];
    float (*qs)[68]  = (float(*)[68]) sm;
    float (*ks)[68]  = (float(*)[68])(sm + 64*68);
    float (*GA)[65]  = (float(*)[65])(sm + 2*64*68);
    float (*buf)[132]= (float(*)[132])(sm + 2*64*68 + 64*65);   // Sp, then V

    const int c  = blockIdx.x;
    const int bh = blockIdx.y;
    const int b = bh >> 4, h = bh & 15;
    const int tid = threadIdx.x;
    const int m0 = b * L_ + c * CHUNK;
    const size_t sbase = (size_t)(bh * NCHUNK + c) * (DK * DV);

    for (int e = tid; e < CHUNK*DK; e += 256) {
        int t = e >> 6, d = e & 63;
        size_t gi = (size_t)(m0 + t)*NQK + h*DK + d;
        qs[t][d] = g_q[gi];
        ks[t][d] = g_k[gi];
    }
    for (int e = tid; e < DK*DV; e += 256) {
        int t = e >> 7, j = e & 127;
        buf[t][j] = g_S[sbase + e];
    }
    __syncthreads();

    for (int e = tid; e < CHUNK*CHUNK; e += 256) {
        int t = e >> 6, s = e & 63;
        float acc = 0.f;
        if (s <= t) {
            const float4* qp = (const float4*)&qs[t][0];
            const float4* kp = (const float4*)&ks[s][0];
#pragma unroll
            for (int d4 = 0; d4 < 16; ++d4) {
                float4 qa = qp[d4], kk4 = kp[d4];
                acc = fmaf(qa.x, kk4.x, acc);
                acc = fmaf(qa.y, kk4.y, acc);
                acc = fmaf(qa.z, kk4.z, acc);
                acc = fmaf(qa.w, kk4.w, acc);
            }
        }
        GA[t][s] = acc;
    }

    const int t  = tid >> 2;
    const int qq = tid & 3;
    float o[32];
#pragma unroll
    for (int jj = 0; jj < 32; ++jj) o[jj] = 0.f;

    for (int d = 0; d < DK; ++d) {
        float qv = qs[t][d];
        const float4* sp4 = (const float4*)&buf[d][qq*32];
#pragma unroll
        for (int j4 = 0; j4 < 8; ++j4) {
            float4 vv = sp4[j4];
            o[j4*4+0] = fmaf(qv, vv.x, o[j4*4+0]);
            o[j4*4+1] = fmaf(qv, vv.y, o[j4*4+1]);
            o[j4*4+2] = fmaf(qv, vv.z, o[j4*4+2]);
            o[j4*4+3] = fmaf(qv, vv.w, o[j4*4+3]);
        }
    }
    __syncthreads();
    for (int e = tid; e < CHUNK*DV; e += 256) {
        int s = e >> 7, j = e & 127;
        buf[s][j] = g_v[(size_t)(m0 + s)*D_ + h*DV + j];
    }
    __syncthreads();
    for (int s = 0; s <= t; ++s) {
        float av = GA[t][s];
        const float4* vp4 = (const float4*)&buf[s][qq*32];
#pragma unroll
        for (int j4 = 0; j4 < 8; ++j4) {
            float4 vv = vp4[j4];
            o[j4*4+0] = fmaf(av, vv.x, o[j4*4+0]);
            o[j4*4+1] = fmaf(av, vv.y, o[j4*4+1]);
            o[j4*4+2] = fmaf(av, vv.z, o[j4*4+2]);
            o[j4*4+3] = fmaf(av, vv.w, o[j4*4+3]);
        }
    }

    float s1 = 0.f;
#pragma unroll
    for (int jj = 0; jj < 32; ++jj) s1 += o[jj];
    s1 += __shfl_xor_sync(0xffffffffu, s1, 1);
    s1 += __shfl_xor_sync(0xffffffffu, s1, 2);
    float mean = s1 * (1.f/128.f);
    float s2 = 0.f;
#pragma unroll
    for (int jj = 0; jj < 32; ++jj) { float dv = o[jj] - mean; s2 = fmaf(dv, dv, s2); }
    s2 += __shfl_xor_sync(0xffffffffu, s2, 1);
    s2 += __shfl_xor_sync(0xffffffffu, s2, 2);
    float rstd = rsqrtf(s2 * (1.f/128.f) + LN_EPS);
    const int m = m0 + t;
    const float* gpp = g_gp + (size_t)m*D_ + h*DV + qq*32;
    __half*      yp  = g_yh + (size_t)m*D_ + h*DV + qq*32;
#pragma unroll
    for (int jj = 0; jj < 32; ++jj) {
        float gv = gpp[jj];
        float si = gv / (1.f + __expf(-gv));
        yp[jj] = __float2half_rn(si * ((o[jj] - mean) * rstd));
    }
}

// ---------------- host driver -------------------------------------------------
extern "C" void kernel_launch(void* const* d_in, const int* in_sizes, int n_in,
                              void* d_out, int out_size)
{
    const float* x    = (const float*)d_in[0];
    const float* Wq   = (const float*)d_in[1];
    const float* Wk   = (const float*)d_in[2];
    const float* Wkg1 = (const float*)d_in[3];
    const float* Wkg2 = (const float*)d_in[4];
    const float* bkg2 = (const float*)d_in[5];
    const float* Wv   = (const float*)d_in[6];
    const float* Wg   = (const float*)d_in[7];
    const float* bg   = (const float*)d_in[8];
    const float* Wo   = (const float*)d_in[9];
    float* out = (float*)d_out;

    float *pq, *pk, *pv, *pgp, *pkg1;
    __half *pyh, *pxh, *pwh;
    cudaGetSymbolAddress((void**)&pq,   g_q);
    cudaGetSymbolAddress((void**)&pk,   g_k);
    cudaGetSymbolAddress((void**)&pv,   g_v);
    cudaGetSymbolAddress((void**)&pgp,  g_gp);
    cudaGetSymbolAddress((void**)&pkg1, g_kg1);
    cudaGetSymbolAddress((void**)&pyh,  g_yh);
    cudaGetSymbolAddress((void**)&pxh,  g_xh);
    cudaGetSymbolAddress((void**)&pwh,  g_wh);

    cudaFuncSetAttribute(f16_gemm_multi, cudaFuncAttributeMaxDynamicSharedMemorySize, GEMM_SMEM_BYTES);
    cudaFuncSetAttribute(state_kernel,   cudaFuncAttributeMaxDynamicSharedMemorySize, STATE_SMEM);
    cudaFuncSetAttribute(output_kernel,  cudaFuncAttributeMaxDynamicSharedMemorySize, OUT_SMEM);

    // single fused fp16 convert launch (x + all weights)
    cvt_all_kernel<<<dim3((M_*D_/8 + 255)/256, 6), 256>>>(
        (const float4*)x, (const float4*)Wq, (const float4*)Wk,
        (const float4*)Wv, (const float4*)Wg, (const float4*)Wo,
        pxh, pwh);

    // merged projection GEMMs: tiles [0,8)=Wq, [8,16)=Wk, [16,32)=Wv, [32,48)=Wg
    f16_gemm_multi<<<dim3(48, M_/BM), 256, GEMM_SMEM_BYTES>>>(
        pxh, pwh + WOFF_Q, pwh + WOFF_K, pwh + WOFF_V, pwh + WOFF_G, bg,
        pq, pk, pv, pgp,
        D_,
        8, 16, 32,
        0, 0, 0,
        NQK, NQK, D_, D_,
        1.f, SCALE_QK, 1.f, 1.f);
    kg1_kernel<<<M_/16, 256>>>(x, Wkg1, pkg1);
    gate_kernel<<<M_, 256>>>(Wkg2, bkg2);

    // gate cumsum + q/k transform (parallel), then recurrence
    prep_kernel<<<dim3(NCHUNK, B_*H_), 64>>>();
    state_kernel<<<dim3(4, B_*H_), 128, STATE_SMEM>>>();
    output_kernel<<<dim3(NCHUNK, B_*H_), 256, OUT_SMEM>>>();

    // out = y @ Wo^T; tiles [8,16) read Wo rows 1024.. via pre-offset pointer
    f16_gemm_multi<<<dim3(16, M_/BM), 256, GEMM_SMEM_BYTES>>>(
        pyh, pwh + WOFF_O, pwh + WOFF_O + (size_t)1024 * D_, pwh + WOFF_O, pwh + WOFF_O, nullptr,
        out, out, out, out,
        D_,
        8, 999, 999,
        1024, 0, 0,
        D_, D_, D_, D_,
        1.f, 1.f, 1.f, 1.f);
}

// round 16
// speedup vs baseline: 1.9911x; 1.2481x over previous
#include <cuda_runtime.h>
#include <cuda_fp16.h>
#include <cstdint>
#include <math.h>

// Problem dims (fixed)
#define B_      2
#define L_      2048
#define D_      2048
#define M_      4096          // B*L
#define H_      16
#define DK      64
#define DV      128
#define NQK     1024          // H*DK
#define CHUNK   64
#define NCHUNK  32            // L / CHUNK
#define SCALE_QK 0.08838834764831845f   // 128^-0.5
#define INV_NORM 0.0625f                 // 1/16
#define LN_EPS   1e-5f

// ---------------- scratch (static device globals; no allocation) -------------
__device__ float  g_q   [(size_t)M_ * NQK];   // after prep: q * e^G
__device__ float  g_k   [(size_t)M_ * NQK];   // after prep: k * e^-G (pre-scaled)
__device__ float  g_gate[(size_t)M_ * NQK];
__device__ float  g_kg1 [(size_t)M_ * 16];
__device__ float  g_v   [(size_t)M_ * D_];
__device__ float  g_gp  [(size_t)M_ * D_];
__device__ __half g_yh  [(size_t)M_ * D_];    // fp16 y for final GEMM
__device__ float  g_S   [(size_t)B_ * H_ * NCHUNK * DK * DV];
__device__ float  g_E   [(size_t)B_ * H_ * NCHUNK * DK];      // per-chunk decay
__device__ __half g_xh  [(size_t)M_ * D_];    // fp16 x
__device__ __half g_wh  [(size_t)8192 * D_];  // fp16 Wq|Wk|Wv|Wg|Wo

#define WOFF_Q  0
#define WOFF_K  ((size_t)1024 * D_)
#define WOFF_V  ((size_t)2048 * D_)
#define WOFF_G  ((size_t)4096 * D_)
#define WOFF_O  ((size_t)6144 * D_)

// ======================= PTX helpers (non-'a' features only) ==================
__device__ __forceinline__ uint32_t smem_u32(const void* p) {
    uint32_t a;
    asm("{ .reg .u64 t; cvta.to.shared.u64 t, %1; cvt.u32.u64 %0, t; }" : "=r"(a) : "l"(p));
    return a;
}
__device__ __forceinline__ void cp_async16(uint32_t dst, const void* src) {
    asm volatile("cp.async.cg.shared.global [%0], [%1], 16;" :: "r"(dst), "l"(src) : "memory");
}
#define CP_COMMIT() asm volatile("cp.async.commit_group;" ::: "memory")
#define CP_WAIT(N)  asm volatile("cp.async.wait_group %0;" :: "n"(N) : "memory")

// fp16 MMA m16n8k16, fp32 accumulate (sm_80 baseline)
__device__ __forceinline__ void mma_f16(float c[4], const uint32_t a[4], const uint32_t b[2]) {
    asm volatile(
        "mma.sync.aligned.m16n8k16.row.col.f32.f16.f16.f32 "
        "{%0,%1,%2,%3}, {%4,%5,%6,%7}, {%8,%9}, {%0,%1,%2,%3};"
        : "+f"(c[0]), "+f"(c[1]), "+f"(c[2]), "+f"(c[3])
        : "r"(a[0]), "r"(a[1]), "r"(a[2]), "r"(a[3]), "r"(b[0]), "r"(b[1]));
}
// warp-collective 4x 8x8 b16 matrix load
__device__ __forceinline__ void ldsm_x4(uint32_t r[4], uint32_t addr) {
    asm volatile("ldmatrix.sync.aligned.m8n8.x4.shared.b16 {%0,%1,%2,%3}, [%4];"
        : "=r"(r[0]), "=r"(r[1]), "=r"(r[2]), "=r"(r[3]) : "r"(addr));
}

// ---------------- fused fp16 convert pass (segmented) -------------------------
__global__ __launch_bounds__(256) void cvt_all_kernel(
    const float4* __restrict__ x,
    const float4* __restrict__ Wq, const float4* __restrict__ Wk,
    const float4* __restrict__ Wv, const float4* __restrict__ Wg,
    const float4* __restrict__ Wo,
    __half* __restrict__ dx, __half* __restrict__ dw)
{
    const int seg = blockIdx.y;
    const float4* src;
    __half* dst;
    int n8;
    switch (seg) {
        case 0: src = x;  dst = dx;            n8 = M_*D_/8;   break;
        case 1: src = Wq; dst = dw + WOFF_Q;   n8 = 1024*D_/8; break;
        case 2: src = Wk; dst = dw + WOFF_K;   n8 = 1024*D_/8; break;
        case 3: src = Wv; dst = dw + WOFF_V;   n8 = 2048*D_/8; break;
        case 4: src = Wg; dst = dw + WOFF_G;   n8 = 2048*D_/8; break;
        default:src = Wo; dst = dw + WOFF_O;   n8 = 2048*D_/8; break;
    }
    int i = blockIdx.x * blockDim.x + threadIdx.x;
    if (i < n8) {
        float4 v0 = src[2*i], v1 = src[2*i+1];
        __half2 h0 = __floats2half2_rn(v0.x, v0.y);
        __half2 h1 = __floats2half2_rn(v0.z, v0.w);
        __half2 h2 = __floats2half2_rn(v1.x, v1.y);
        __half2 h3 = __floats2half2_rn(v1.z, v1.w);
        uint4 u;
        u.x = *(uint32_t*)&h0; u.y = *(uint32_t*)&h1;
        u.z = *(uint32_t*)&h2; u.w = *(uint32_t*)&h3;
        *(uint4*)(dst + (size_t)i*8) = u;
    }
}

// ======================= fp16 GEMM (mma.sync m16n8k16), multi-target ==========
#define BM 128
#define BN 128
#define BK 64                              // halves per K-tile
#define PITCH32 36                         // u32 per smem row (32 data + 4 pad)
#define TSTRIDE32 (128*PITCH32)            // u32 per tile stage
#define GEMM_SMEM_BYTES (4*TSTRIDE32*4)    // A[2] + B[2] = 73728

__global__ __launch_bounds__(256, 2)
void f16_gemm_multi(
    const __half* __restrict__ A,
    const __half* __restrict__ W0, const __half* __restrict__ W1,
    const __half* __restrict__ W2, const __half* __restrict__ W3,
    const float* __restrict__ bias3,
    float* __restrict__ C0, float* __restrict__ C1,
    float* __restrict__ C2, float* __restrict__ C3,
    int K,
    int s1, int s2, int s3,
    int cb1, int cb2, int cb3,
    int N0, int N1, int N2, int N3,
    float a0, float a1, float a2, float a3)
{
    extern __shared__ uint32_t smu[];
    uint32_t* Asm = smu;
    uint32_t* Bsm = smu + 2*TSTRIDE32;
    const uint32_t Abase_s = smem_u32(Asm);
    const uint32_t Bbase_s = smem_u32(Bsm);

    const int c = blockIdx.x;
    const int sel = (c >= s3) ? 3 : (c >= s2) ? 2 : (c >= s1) ? 1 : 0;
    const __half* W = (sel == 0) ? W0 : (sel == 1) ? W1 : (sel == 2) ? W2 : W3;
    float*        C = (sel == 0) ? C0 : (sel == 1) ? C1 : (sel == 2) ? C2 : C3;
    const int start   = (sel == 0) ? 0 : (sel == 1) ? s1 : (sel == 2) ? s2 : s3;
    const int colbase = (sel == 0) ? 0 : (sel == 1) ? cb1 : (sel == 2) ? cb2 : cb3;
    const int N       = (sel == 0) ? N0 : (sel == 1) ? N1 : (sel == 2) ? N2 : N3;
    const float alpha = (sel == 0) ? a0 : (sel == 1) ? a1 : (sel == 2) ? a2 : a3;
    const float* bias = (sel == 3) ? bias3 : nullptr;

    const int tid = threadIdx.x;
    const int wid = tid >> 5;
    const int lane = tid & 31;
    const int g  = lane >> 2;
    const int t4 = lane & 3;
    const int wm = wid >> 2;
    const int wn = wid & 3;
    const int m0 = blockIdx.y * BM;
    const int wrow = (c - start) * BN;
    const int n0g = wrow + colbase;

    const int arow = (lane & 7) + ((lane >> 3) & 1) * 8;
    const int acol = ((lane >> 4) & 1) * 4;
    const int brow = lane & 7;
    const int bnts = (lane >> 4) & 1;
    const int bcol = ((lane >> 3) & 1) * 4;

    const __half* Ag = A + (size_t)m0   * K;
    const __half* Bg = W + (size_t)wrow * K;

    float cacc[4][4][4];
#pragma unroll
    for (int i = 0; i < 4; ++i)
#pragma unroll
        for (int j = 0; j < 4; ++j)
#pragma unroll
            for (int e = 0; e < 4; ++e) cacc[i][j][e] = 0.f;

    const int niter = K / BK;

    auto load_tile = [&](int kt, int s) {
        const int k0 = kt * BK;
        const uint32_t sa = Abase_s + (uint32_t)s * TSTRIDE32 * 4;
        const uint32_t sb = Bbase_s + (uint32_t)s * TSTRIDE32 * 4;
#pragma unroll
        for (int i = 0; i < 4; ++i) {
            int idx = tid + 256*i;
            int r = idx >> 3, sg = idx & 7;
            cp_async16(sa + (uint32_t)(r*PITCH32 + sg*4)*4, Ag + (size_t)r*K + k0 + sg*8);
        }
#pragma unroll
        for (int i = 0; i < 4; ++i) {
            int idx = tid + 256*i;
            int r = idx >> 3, sg = idx & 7;
            cp_async16(sb + (uint32_t)(r*PITCH32 + sg*4)*4, Bg + (size_t)r*K + k0 + sg*8);
        }
    };

    load_tile(0, 0);
    CP_COMMIT();

    for (int kt = 0; kt < niter; ++kt) {
        const int s = kt & 1;
        if (kt + 1 < niter) {
            load_tile(kt + 1, s ^ 1);
            CP_COMMIT();
            CP_WAIT(1);
        } else {
            CP_WAIT(0);
        }
        __syncthreads();

        const uint32_t As_addr = Abase_s + (uint32_t)s * TSTRIDE32 * 4;
        const uint32_t Bs_addr = Bbase_s + (uint32_t)s * TSTRIDE32 * 4;
#pragma unroll
        for (int kk = 0; kk < 4; ++kk) {
            uint32_t af[4][4];
#pragma unroll
            for (int mt = 0; mt < 4; ++mt) {
                uint32_t a_addr = As_addr +
                    (uint32_t)(((wm*64 + mt*16 + arow) * PITCH32) + kk*8 + acol) * 4;
                ldsm_x4(af[mt], a_addr);
            }
            uint32_t bf[4][2];
#pragma unroll
            for (int p = 0; p < 2; ++p) {
                uint32_t tmp[4];
                uint32_t b_addr = Bs_addr +
                    (uint32_t)(((wn*32 + (2*p + bnts)*8 + brow) * PITCH32) + kk*8 + bcol) * 4;
                ldsm_x4(tmp, b_addr);
                bf[2*p  ][0] = tmp[0]; bf[2*p  ][1] = tmp[1];
                bf[2*p+1][0] = tmp[2]; bf[2*p+1][1] = tmp[3];
            }
#pragma unroll
            for (int mt = 0; mt < 4; ++mt)
#pragma unroll
                for (int nt = 0; nt < 4; ++nt)
                    mma_f16(cacc[mt][nt], af[mt], bf[nt]);
        }
        __syncthreads();
    }

#pragma unroll
    for (int mt = 0; mt < 4; ++mt) {
#pragma unroll
        for (int nt = 0; nt < 4; ++nt) {
            const int col = n0g + wn*32 + nt*8 + 2*t4;
            float b0 = bias ? __ldg(bias + col)     : 0.f;
            float b1 = bias ? __ldg(bias + col + 1) : 0.f;
            const int r0 = m0 + wm*64 + mt*16 + g;
            float2 v0 = make_float2(cacc[mt][nt][0]*alpha + b0, cacc[mt][nt][1]*alpha + b1);
            float2 v1 = make_float2(cacc[mt][nt][2]*alpha + b0, cacc[mt][nt][3]*alpha + b1);
            *(float2*)(C + (size_t)r0      * N + col) = v0;
            *(float2*)(C + (size_t)(r0+8)  * N + col) = v1;
        }
    }
}

// ---------------- kg1 = x @ Wkg1^T  ------------------------------------------
__global__ __launch_bounds__(256) void kg1_kernel(
    const float* __restrict__ x, const float* __restrict__ Wkg1,
    float* __restrict__ out)
{
    __shared__ float xs[16][68];
    __shared__ float ws[16][68];
    const int tid = threadIdx.x;
    const int tx = tid & 15;
    const int ty = tid >> 4;
    const int m0 = blockIdx.x * 16;
    const int lrow = tid >> 4;
    const int lcol = (tid & 15) * 4;
    float acc = 0.f;
    for (int kt = 0; kt < D_; kt += 64) {
        float4 xv = *(const float4*)(x    + (size_t)(m0 + lrow)*D_ + kt + lcol);
        float4 wv = *(const float4*)(Wkg1 + (size_t)lrow*D_        + kt + lcol);
        *(float4*)&xs[lrow][lcol] = xv;
        *(float4*)&ws[lrow][lcol] = wv;
        __syncthreads();
#pragma unroll
        for (int kk = 0; kk < 64; ++kk)
            acc = fmaf(xs[ty][kk], ws[tx][kk], acc);
        __syncthreads();
    }
    out[(size_t)(m0 + ty)*16 + tx] = acc;
}

// ---------------- gate = log_sigmoid(kg1 @ Wkg2^T + bkg2) / 16 ---------------
__global__ __launch_bounds__(256) void gate_kernel(
    const float* __restrict__ Wkg2, const float* __restrict__ bkg2)
{
    __shared__ float row[16];
    const int tid = threadIdx.x;
    const int m = blockIdx.x;
    if (tid < 16) row[tid] = g_kg1[(size_t)m*16 + tid];
    __syncthreads();
#pragma unroll
    for (int i = 0; i < 4; ++i) {
        int n = i*256 + tid;
        const float4* wp = (const float4*)(Wkg2 + (size_t)n*16);
        float4 w0 = wp[0], w1 = wp[1], w2 = wp[2], w3 = wp[3];
        float acc = bkg2[n];
        acc += row[0]*w0.x + row[1]*w0.y + row[2]*w0.z + row[3]*w0.w;
        acc += row[4]*w1.x + row[5]*w1.y + row[6]*w1.z + row[7]*w1.w;
        acc += row[8]*w2.x + row[9]*w2.y + row[10]*w2.z + row[11]*w2.w;
        acc += row[12]*w3.x + row[13]*w3.y + row[14]*w3.z + row[15]*w3.w;
        float z = acc;
        float e  = __expf(-fabsf(z));
        float ls = fminf(z, 0.f) - __logf(1.f + e);
        g_gate[(size_t)m*NQK + n] = ls * INV_NORM;
    }
}

// ---------------- prep v2: smem-staged cumsum + parallel transform -----------
// grid (NCHUNK, BH), 256 threads. gs pitch 68 (272B rows, float4-aligned).
__global__ __launch_bounds__(256) void prep_kernel()
{
    __shared__ float gs[64][68];
    const int c  = blockIdx.x;
    const int bh = blockIdx.y;
    const int b = bh >> 4, h = bh & 15;
    const int tid = threadIdx.x;
    const int m0 = b * L_ + c * CHUNK;

    // stage 64x64 gate tile (coalesced float4; 272B row stride keeps alignment)
    for (int e = tid; e < 64*16; e += 256) {
        int t = e >> 4, c4 = (e & 15) * 4;
        *(float4*)&gs[t][c4] =
            *(const float4*)(g_gate + (size_t)(m0 + t)*NQK + h*DK + c4);
    }
    __syncthreads();
    // serial cumsum per dk lane (LDS-latency chain, not gmem)
    if (tid < 64) {
        float run = 0.f;
#pragma unroll
        for (int t = 0; t < CHUNK; ++t) {
            run += gs[t][tid];
            gs[t][tid] = run;
        }
        g_E[(size_t)(bh * NCHUNK + c) * DK + tid] = __expf(run);
    }
    __syncthreads();
    // parallel transform of q, k
    for (int e = tid; e < 64*64; e += 256) {
        int t = e >> 6, d = e & 63;
        float G = gs[t][d];
        size_t gi = (size_t)(m0 + t)*NQK + h*DK + d;
        g_q[gi] *= __expf(G);
        g_k[gi] *= __expf(-G);
    }
}

// ---------------- pass 1: chunk states, cp.async pipelined -------------------
#define SKP_K 68
#define SKP_V 36
#define STATE_SMEM ((2*64*SKP_K + 2*64*SKP_V)*4)

__global__ __launch_bounds__(128) void state_kernel()
{
    extern __shared__ float sms[];
    float* khs = sms;                    // [2][64][SKP_K]
    float* vvs = sms + 2*64*SKP_K;       // [2][64][SKP_V]
    const uint32_t kh_s = smem_u32(khs);
    const uint32_t vv_s = smem_u32(vvs);

    const int bq = blockIdx.x;
    const int bh = blockIdx.y;
    const int b = bh >> 4, h = bh & 15;
    const int tid = threadIdx.x;
    const int ty = tid >> 3;
    const int tx = tid & 7;
    const int mb = b * L_;

    auto prefetch = [&](int c, int s) {
        const int m0 = mb + c * CHUNK;
        const uint32_t ka = kh_s + (uint32_t)s * 64*SKP_K*4;
        const uint32_t va = vv_s + (uint32_t)s * 64*SKP_V*4;
#pragma unroll
        for (int i = 0; i < 8; ++i) {
            int e = tid + 128*i;
            int t = e >> 4, q4 = (e & 15) * 4;
            cp_async16(ka + (uint32_t)(t*SKP_K + q4)*4,
                       g_k + (size_t)(m0 + t)*NQK + h*DK + q4);
        }
#pragma unroll
        for (int i = 0; i < 4; ++i) {
            int e = tid + 128*i;
            int t = e >> 3, q4 = (e & 7) * 4;
            cp_async16(va + (uint32_t)(t*SKP_V + q4)*4,
                       g_v + (size_t)(m0 + t)*D_ + h*DV + bq*32 + q4);
        }
    };

    float S[4][4];
#pragma unroll
    for (int dd = 0; dd < 4; ++dd)
#pragma unroll
        for (int jj = 0; jj < 4; ++jj) S[dd][jj] = 0.f;

    prefetch(0, 0);
    CP_COMMIT();

    for (int c = 0; c < NCHUNK; ++c) {
        const int s = c & 1;
        CP_WAIT(0);
        __syncthreads();
        if (c + 1 < NCHUNK) {
            prefetch(c + 1, s ^ 1);
            CP_COMMIT();
        }

        float* sp = g_S + (size_t)(bh * NCHUNK + c) * (DK * DV) + (size_t)bq * 32;
#pragma unroll
        for (int dd = 0; dd < 4; ++dd)
            *(float4*)(sp + (size_t)(ty*4 + dd)*DV + tx*4) =
                make_float4(S[dd][0], S[dd][1], S[dd][2], S[dd][3]);

        float acc[4][4];
#pragma unroll
        for (int dd = 0; dd < 4; ++dd)
#pragma unroll
            for (int jj = 0; jj < 4; ++jj) acc[dd][jj] = 0.f;

        const float* kb = khs + s * 64*SKP_K;
        const float* vb = vvs + s * 64*SKP_V;
        for (int t = 0; t < CHUNK; ++t) {
            float4 kv = *(const float4*)(kb + t*SKP_K + ty*4);
            float4 vv4 = *(const float4*)(vb + t*SKP_V + tx*4);
            float ka[4] = {kv.x, kv.y, kv.z, kv.w};
            float va[4] = {vv4.x, vv4.y, vv4.z, vv4.w};
#pragma unroll
            for (int dd = 0; dd < 4; ++dd)
#pragma unroll
                for (int jj = 0; jj < 4; ++jj)
                    acc[dd][jj] = fmaf(ka[dd], va[jj], acc[dd][jj]);
        }

        const float* ep = g_E + (size_t)(bh * NCHUNK + c) * DK + ty*4;
        float E[4] = {ep[0], ep[1], ep[2], ep[3]};
#pragma unroll
        for (int dd = 0; dd < 4; ++dd)
#pragma unroll
            for (int jj = 0; jj < 4; ++jj)
                S[dd][jj] = E[dd] * (S[dd][jj] + acc[dd][jj]);
    }
}

// ---------------- pass 2 v3: register-blocked (2 rows/thread) -----------------
#define OUT_SMEM ((2*64*68 + 64*65 + 64*132)*4)

__global__ __launch_bounds__(256) void output_kernel()
{
    extern __shared__ float sm[];
    float (*qs)[68]  = (float(*)[68]) sm;
    float (*ks)[68]  = (float(*)[68])(sm + 64*68);
    float (*GA)[65]  = (float(*)[65])(sm + 2*64*68);            // scalar access only
    float (*buf)[132]= (float(*)[132])(sm + 2*64*68 + 64*65);   // Sp, then V

    const int c  = blockIdx.x;
    const int bh = blockIdx.y;
    const int b = bh >> 4, h = bh & 15;
    const int tid = threadIdx.x;
    const int m0 = b * L_ + c * CHUNK;
    const size_t sbase = (size_t)(bh * NCHUNK + c) * (DK * DV);

    // load q~, k^ and S_prev
    for (int e = tid; e < CHUNK*DK; e += 256) {
        int t = e >> 6, d = e & 63;
        size_t gi = (size_t)(m0 + t)*NQK + h*DK + d;
        qs[t][d] = g_q[gi];
        ks[t][d] = g_k[gi];
    }
    for (int e = tid; e < DK*DV; e += 256) {
        int t = e >> 7, j = e & 127;
        buf[t][j] = g_S[sbase + e];
    }
    __syncthreads();

    // ---- phase A: A[t][s] = (s<=t) ? q~_t . k^_s : 0 (2 rows x 8 strided s) --
    {
        const int tA = tid >> 3;           // 0..31 -> rows tA, tA+32
        const int sq = tid & 7;            // s = sq + 8*j
        float accA[2][8];
#pragma unroll
        for (int r = 0; r < 2; ++r)
#pragma unroll
            for (int j = 0; j < 8; ++j) accA[r][j] = 0.f;

        for (int d4 = 0; d4 < 16; ++d4) {
            float4 q0 = *(const float4*)&qs[tA][d4*4];
            float4 q1 = *(const float4*)&qs[tA+32][d4*4];
#pragma unroll
            for (int j = 0; j < 8; ++j) {
                float4 kv = *(const float4*)&ks[sq + 8*j][d4*4];
                accA[0][j] = fmaf(q0.x, kv.x, accA[0][j]);
                accA[0][j] = fmaf(q0.y, kv.y, accA[0][j]);
                accA[0][j] = fmaf(q0.z, kv.z, accA[0][j]);
                accA[0][j] = fmaf(q0.w, kv.w, accA[0][j]);
                accA[1][j] = fmaf(q1.x, kv.x, accA[1][j]);
                accA[1][j] = fmaf(q1.y, kv.y, accA[1][j]);
                accA[1][j] = fmaf(q1.z, kv.z, accA[1][j]);
                accA[1][j] = fmaf(q1.w, kv.w, accA[1][j]);
            }
        }
#pragma unroll
        for (int j = 0; j < 8; ++j) {
            int s = sq + 8*j;
            GA[tA][s]      = (s <= tA)      ? accA[0][j] : 0.f;
            GA[tA+32][s]   = (s <= tA+32)   ? accA[1][j] : 0.f;
        }
    }

    // ---- phase 1: o += q~ @ S_prev (buf=Sp), 2 rows x 16 cols per thread ----
    const int to = tid >> 3;       // 0..31 -> rows to, to+32
    const int qq = tid & 7;        // cols qq*16..+15
    float o[2][16];
#pragma unroll
    for (int r = 0; r < 2; ++r)
#pragma unroll
        for (int jj = 0; jj < 16; ++jj) o[r][jj] = 0.f;

    for (int d = 0; d < DK; ++d) {
        float q0 = qs[to][d];
        float q1 = qs[to+32][d];
        const float4* sp4 = (const float4*)&buf[d][qq*16];
#pragma unroll
        for (int j4 = 0; j4 < 4; ++j4) {
            float4 vv = sp4[j4];
            o[0][j4*4+0] = fmaf(q0, vv.x, o[0][j4*4+0]);
            o[0][j4*4+1] = fmaf(q0, vv.y, o[0][j4*4+1]);
            o[0][j4*4+2] = fmaf(q0, vv.z, o[0][j4*4+2]);
            o[0][j4*4+3] = fmaf(q0, vv.w, o[0][j4*4+3]);
            o[1][j4*4+0] = fmaf(q1, vv.x, o[1][j4*4+0]);
            o[1][j4*4+1] = fmaf(q1, vv.y, o[1][j4*4+1]);
            o[1][j4*4+2] = fmaf(q1, vv.z, o[1][j4*4+2]);
            o[1][j4*4+3] = fmaf(q1, vv.w, o[1][j4*4+3]);
        }
    }
    __syncthreads();   // GA writes visible; buf(Sp) reads done
    // reload buf with V
    for (int e = tid; e < CHUNK*DV; e += 256) {
        int s = e >> 7, j = e & 127;
        buf[s][j] = g_v[(size_t)(m0 + s)*D_ + h*DV + j];
    }
    __syncthreads();
    // ---- phase 2: o += A @ V (masked entries of GA are 0) --------------------
    for (int s = 0; s < CHUNK; ++s) {
        float a0 = GA[to][s];
        float a1 = GA[to+32][s];
        const float4* vp4 = (const float4*)&buf[s][qq*16];
#pragma unroll
        for (int j4 = 0; j4 < 4; ++j4) {
            float4 vv = vp4[j4];
            o[0][j4*4+0] = fmaf(a0, vv.x, o[0][j4*4+0]);
            o[0][j4*4+1] = fmaf(a0, vv.y, o[0][j4*4+1]);
            o[0][j4*4+2] = fmaf(a0, vv.z, o[0][j4*4+2]);
            o[0][j4*4+3] = fmaf(a0, vv.w, o[0][j4*4+3]);
            o[1][j4*4+0] = fmaf(a1, vv.x, o[1][j4*4+0]);
            o[1][j4*4+1] = fmaf(a1, vv.y, o[1][j4*4+1]);
            o[1][j4*4+2] = fmaf(a1, vv.z, o[1][j4*4+2]);
            o[1][j4*4+3] = fmaf(a1, vv.w, o[1][j4*4+3]);
        }
    }

    // ---- LayerNorm per row (8 threads per row: shfl over qq bits 1|2|4) -----
#pragma unroll
    for (int r = 0; r < 2; ++r) {
        float s1 = 0.f;
#pragma unroll
        for (int jj = 0; jj < 16; ++jj) s1 += o[r][jj];
        s1 += __shfl_xor_sync(0xffffffffu, s1, 1);
        s1 += __shfl_xor_sync(0xffffffffu, s1, 2);
        s1 += __shfl_xor_sync(0xffffffffu, s1, 4);
        float mean = s1 * (1.f/128.f);
        float s2 = 0.f;
#pragma unroll
        for (int jj = 0; jj < 16; ++jj) { float dv = o[r][jj] - mean; s2 = fmaf(dv, dv, s2); }
        s2 += __shfl_xor_sync(0xffffffffu, s2, 1);
        s2 += __shfl_xor_sync(0xffffffffu, s2, 2);
        s2 += __shfl_xor_sync(0xffffffffu, s2, 4);
        float rstd = rsqrtf(s2 * (1.f/128.f) + LN_EPS);
        const int m = m0 + to + r*32;
        const float* gpp = g_gp + (size_t)m*D_ + h*DV + qq*16;
        __half*      yp  = g_yh + (size_t)m*D_ + h*DV + qq*16;
#pragma unroll
        for (int jj = 0; jj < 16; ++jj) {
            float gv = gpp[jj];
            float si = gv / (1.f + __expf(-gv));
            yp[jj] = __float2half_rn(si * ((o[r][jj] - mean) * rstd));
        }
    }
}

// ---------------- host driver -------------------------------------------------
extern "C" void kernel_launch(void* const* d_in, const int* in_sizes, int n_in,
                              void* d_out, int out_size)
{
    const float* x    = (const float*)d_in[0];
    const float* Wq   = (const float*)d_in[1];
    const float* Wk   = (const float*)d_in[2];
    const float* Wkg1 = (const float*)d_in[3];
    const float* Wkg2 = (const float*)d_in[4];
    const float* bkg2 = (const float*)d_in[5];
    const float* Wv   = (const float*)d_in[6];
    const float* Wg   = (const float*)d_in[7];
    const float* bg   = (const float*)d_in[8];
    const float* Wo   = (const float*)d_in[9];
    float* out = (float*)d_out;

    float *pq, *pk, *pv, *pgp, *pkg1;
    __half *pyh, *pxh, *pwh;
    cudaGetSymbolAddress((void**)&pq,   g_q);
    cudaGetSymbolAddress((void**)&pk,   g_k);
    cudaGetSymbolAddress((void**)&pv,   g_v);
    cudaGetSymbolAddress((void**)&pgp,  g_gp);
    cudaGetSymbolAddress((void**)&pkg1, g_kg1);
    cudaGetSymbolAddress((void**)&pyh,  g_yh);
    cudaGetSymbolAddress((void**)&pxh,  g_xh);
    cudaGetSymbolAddress((void**)&pwh,  g_wh);

    cudaFuncSetAttribute(f16_gemm_multi, cudaFuncAttributeMaxDynamicSharedMemorySize, GEMM_SMEM_BYTES);
    cudaFuncSetAttribute(state_kernel,   cudaFuncAttributeMaxDynamicSharedMemorySize, STATE_SMEM);
    cudaFuncSetAttribute(output_kernel,  cudaFuncAttributeMaxDynamicSharedMemorySize, OUT_SMEM);

    // single fused fp16 convert launch (x + all weights)
    cvt_all_kernel<<<dim3((M_*D_/8 + 255)/256, 6), 256>>>(
        (const float4*)x, (const float4*)Wq, (const float4*)Wk,
        (const float4*)Wv, (const float4*)Wg, (const float4*)Wo,
        pxh, pwh);

    // merged projection GEMMs: tiles [0,8)=Wq, [8,16)=Wk, [16,32)=Wv, [32,48)=Wg
    f16_gemm_multi<<<dim3(48, M_/BM), 256, GEMM_SMEM_BYTES>>>(
        pxh, pwh + WOFF_Q, pwh + WOFF_K, pwh + WOFF_V, pwh + WOFF_G, bg,
        pq, pk, pv, pgp,
        D_,
        8, 16, 32,
        0, 0, 0,
        NQK, NQK, D_, D_,
        1.f, SCALE_QK, 1.f, 1.f);
    kg1_kernel<<<M_/16, 256>>>(x, Wkg1, pkg1);
    gate_kernel<<<M_, 256>>>(Wkg2, bkg2);

    // gate cumsum + q/k transform (parallel), then recurrence
    prep_kernel<<<dim3(NCHUNK, B_*H_), 256>>>();
    state_kernel<<<dim3(4, B_*H_), 128, STATE_SMEM>>>();
    output_kernel<<<dim3(NCHUNK, B_*H_), 256, OUT_SMEM>>>();

    // out = y @ Wo^T; tiles [8,16) read Wo rows 1024.. via pre-offset pointer
    f16_gemm_multi<<<dim3(16, M_/BM), 256, GEMM_SMEM_BYTES>>>(
        pyh, pwh + WOFF_O, pwh + WOFF_O + (size_t)1024 * D_, pwh + WOFF_O, pwh + WOFF_O, nullptr,
        out, out, out, out,
        D_,
        8, 999, 999,
        1024, 0, 0,
        D_, D_, D_, D_,
        1.f, 1.f, 1.f, 1.f);
}